// round 3
// baseline (speedup 1.0000x reference)
#include <cuda_runtime.h>
#include <math.h>
#include <stdint.h>

#define BB 64      // batch
#define HH 1024    // hidden
#define VV 2048    // vocab
#define TT 256     // seq len
#define GG 4096    // 4*HH
#define NBLK 128   // persistent grid (<= 148 SMs -> co-resident, barrier-safe)
#define NTHR 128

typedef unsigned long long u64;

// ---------------- scratch (static device globals) ----------------
__device__ float g_hbuf1[2][BB * HH];
__device__ float g_hbuf2[2][BB * HH];
__device__ float g_c[3][BB * HH];
__device__ float g_h3[(TT + 1) * BB * HH];   // slot 0 = zeros; slot t+1 = h3 at step t

// software grid barrier state
__device__ unsigned g_count = 0;
__device__ volatile unsigned g_gen = 0;

// ---------------- f32x2 helpers (sm_103a packed fp32) ----------------
__device__ __forceinline__ u64 ffma2(u64 a, u64 b, u64 c) {
    u64 d;
    asm("fma.rn.f32x2 %0, %1, %2, %3;" : "=l"(d) : "l"(a), "l"(b), "l"(c));
    return d;
}
__device__ __forceinline__ u64 splat2(float w) {
    u64 d;
    asm("mov.b64 %0, {%1, %1};" : "=l"(d) : "f"(w));
    return d;
}
__device__ __forceinline__ void unpack2(u64 v, float& lo, float& hi) {
    asm("mov.b64 {%0, %1}, %2;" : "=f"(lo), "=f"(hi) : "l"(v));
}

// ---------------- software grid barrier ----------------
__device__ __forceinline__ void gbar() {
    __syncthreads();
    if (threadIdx.x == 0) {
        unsigned gen = g_gen;                  // read before arrive
        __threadfence();                       // release prior writes
        unsigned a = atomicAdd(&g_count, 1);
        if (a == NBLK - 1) {
            atomicExch(&g_count, 0);
            __threadfence();
            g_gen = gen + 1;                   // release
        } else {
            while (g_gen == gen) { __nanosleep(32); }
            __threadfence();                   // acquire
        }
    }
    __syncthreads();
}

// ---------------- init ----------------
__global__ void init_zero() {
    int i = blockIdx.x * blockDim.x + threadIdx.x;
    if (i < BB * HH) {
        g_hbuf1[0][i] = 0.f; g_hbuf1[1][i] = 0.f;
        g_hbuf2[0][i] = 0.f; g_hbuf2[1][i] = 0.f;
        g_c[0][i] = 0.f; g_c[1][i] = 0.f; g_c[2][i] = 0.f;
        g_h3[i] = 0.f;
    }
}

// ---------------- persistent recurrence kernel ----------------
// Block (mhalf, jt): batch rows [mhalf*32, +32), hidden units [jt*16, +16), all 4 gates.
// GEMM tile M=32 x N=64 (cols = 4 gates x 16 j), K = 1024 (layer 0) / 2048.
// 128 threads: mg = tid&7 (4 m each, as 2 f32x2 pairs), ng = tid>>3 (4 n each).
__global__ void __launch_bounds__(NTHR) lstm_persist(
    const int*   __restrict__ X,
    const float* __restrict__ W1, const float* __restrict__ b1,
    const float* __restrict__ W2, const float* __restrict__ b2,
    const float* __restrict__ W3, const float* __restrict__ b3)
{
    __shared__ __align__(16) float Xs[2][32][36];   // [buf][k][m], 144B rows (16B aligned)
    __shared__ __align__(16) float Ws[2][32][64];   // [buf][k][c]
    __shared__ float Gs[64][34];                    // [c][m] gate pre-activations

    const int tid   = threadIdx.x;
    const int bid   = blockIdx.x;
    const int mhalf = bid & 1;
    const int jt    = bid >> 1;        // 0..63
    const int j0    = jt * 16;
    const int m0    = mhalf * 32;
    const int mg    = tid & 7;         // 8 groups of 4 m
    const int ng    = tid >> 3;        // 16 groups of 4 n

    const float* W1h = W1 + (size_t)VV * GG;

    for (int t = 0; t < TT; t++) {
        for (int layer = 0; layer < 3; layer++) {
            const float *A, *Bp, *W, *bias;
            float *cbuf, *hout;
            int K;
            if (layer == 0) {
                A = g_hbuf1[t & 1]; Bp = nullptr; W = W1h; bias = b1;
                cbuf = g_c[0]; hout = g_hbuf1[(t + 1) & 1]; K = HH;
            } else if (layer == 1) {
                A = g_hbuf1[(t + 1) & 1]; Bp = g_hbuf2[t & 1]; W = W2; bias = b2;
                cbuf = g_c[1]; hout = g_hbuf2[(t + 1) & 1]; K = 2 * HH;
            } else {
                A = g_hbuf2[(t + 1) & 1]; Bp = g_h3 + (size_t)t * BB * HH; W = W3; bias = b3;
                cbuf = g_c[2]; hout = g_h3 + (size_t)(t + 1) * BB * HH; K = 2 * HH;
            }

            const int nkb = K >> 5;   // 32-k chunks

            // ---- stage chunk 0 ----
            {
                const float* half = A;   // kc = 0 always in first half
#pragma unroll
                for (int i = 0; i < 8; i++) {
                    int idx = tid + i * 128;
                    int kk = idx & 31, m = idx >> 5;
                    Xs[0][kk][m] = half[(size_t)(m0 + m) * HH + kk];
                }
#pragma unroll
                for (int i = 0; i < 4; i++) {
                    int u = tid + i * 128;
                    int kk = u >> 4, cu4 = u & 15;
                    int c = cu4 * 4, g = c >> 4, jj = c & 15;
                    float4 v = *(const float4*)&W[(size_t)kk * GG + g * HH + j0 + jj];
                    *(float4*)&Ws[0][kk][c] = v;
                }
            }
            __syncthreads();

            u64 acc[2][4];
#pragma unroll
            for (int p = 0; p < 2; p++)
#pragma unroll
                for (int n = 0; n < 4; n++) acc[p][n] = 0ULL;

            for (int kb = 0; kb < nkb; kb++) {
                const int cur = kb & 1;
                float xr[8];
                float4 wr[4];
                const bool more = (kb + 1 < nkb);
                if (more) {
                    const int kc = (kb + 1) * 32;
                    const float* half = (layer > 0 && kc >= HH) ? (Bp + (kc - HH)) : (A + kc);
#pragma unroll
                    for (int i = 0; i < 8; i++) {
                        int idx = tid + i * 128;
                        int kk = idx & 31, m = idx >> 5;
                        xr[i] = half[(size_t)(m0 + m) * HH + kk];
                    }
#pragma unroll
                    for (int i = 0; i < 4; i++) {
                        int u = tid + i * 128;
                        int kk = u >> 4, cu4 = u & 15;
                        int c = cu4 * 4, g = c >> 4, jj = c & 15;
                        wr[i] = *(const float4*)&W[(size_t)(kc + kk) * GG + g * HH + j0 + jj];
                    }
                }

                // ---- compute 32 k's ----
#pragma unroll
                for (int kk = 0; kk < 32; kk++) {
                    double2 xd = *(const double2*)&Xs[cur][kk][mg * 4];
                    float4  wf = *(const float4*)&Ws[cur][kk][ng * 4];
                    u64 x0 = __double_as_longlong(xd.x);
                    u64 x1 = __double_as_longlong(xd.y);
                    u64 w0 = splat2(wf.x), w1 = splat2(wf.y);
                    u64 w2 = splat2(wf.z), w3 = splat2(wf.w);
                    acc[0][0] = ffma2(x0, w0, acc[0][0]);
                    acc[1][0] = ffma2(x1, w0, acc[1][0]);
                    acc[0][1] = ffma2(x0, w1, acc[0][1]);
                    acc[1][1] = ffma2(x1, w1, acc[1][1]);
                    acc[0][2] = ffma2(x0, w2, acc[0][2]);
                    acc[1][2] = ffma2(x1, w2, acc[1][2]);
                    acc[0][3] = ffma2(x0, w3, acc[0][3]);
                    acc[1][3] = ffma2(x1, w3, acc[1][3]);
                }
                __syncthreads();
                if (more) {
                    const int nxt = cur ^ 1;
#pragma unroll
                    for (int i = 0; i < 8; i++) {
                        int idx = tid + i * 128;
                        int kk = idx & 31, m = idx >> 5;
                        Xs[nxt][kk][m] = xr[i];
                    }
#pragma unroll
                    for (int i = 0; i < 4; i++) {
                        int u = tid + i * 128;
                        int kk = u >> 4, cu4 = u & 15;
                        *(float4*)&Ws[nxt][kk][cu4 * 4] = wr[i];
                    }
                }
                __syncthreads();
            }

            // ---- epilogue: acc -> Gs ----
#pragma unroll
            for (int n = 0; n < 4; n++) {
                int c = ng * 4 + n;
#pragma unroll
                for (int p = 0; p < 2; p++) {
                    float lo, hi;
                    unpack2(acc[p][n], lo, hi);
                    Gs[c][mg * 4 + 2 * p]     = lo;
                    Gs[c][mg * 4 + 2 * p + 1] = hi;
                }
            }
            __syncthreads();

            // ---- gate nonlinearity + state update ----
#pragma unroll
            for (int i = 0; i < 4; i++) {
                int p  = tid + i * 128;       // 0..511
                int jj = p & 15;
                int m  = p >> 4;              // 0..31
                float f  = Gs[jj][m]      + bias[j0 + jj];
                float ig = Gs[16 + jj][m] + bias[HH + j0 + jj];
                float og = Gs[32 + jj][m] + bias[2 * HH + j0 + jj];
                float ct = Gs[48 + jj][m] + bias[3 * HH + j0 + jj];
                if (layer == 0) {
                    int xid = X[(m0 + m) * TT + t];
                    const float* wrow = W1 + (size_t)xid * GG + j0 + jj;
                    f  += wrow[0];
                    ig += wrow[HH];
                    og += wrow[2 * HH];
                    ct += wrow[3 * HH];
                }
                int idx = (m0 + m) * HH + j0 + jj;
                float c  = cbuf[idx];
                float sf = 1.f / (1.f + __expf(-f));
                float si = 1.f / (1.f + __expf(-ig));
                float so = 1.f / (1.f + __expf(-og));
                float cn = sf * c + si * tanhf(ct);
                float hn = so * tanhf(cn);
                cbuf[idx] = cn;
                hout[idx] = hn;
            }

            gbar();   // all blocks' h visible before next layer/step
        }
    }
}

// ---------------- deferred output GEMM: out = H3 @ Wout + bout (f32x2) ----------------
__global__ void __launch_bounds__(128) out_gemm(
    const float* __restrict__ Wout,
    const float* __restrict__ bout,
    float* __restrict__ out)
{
    const float* Amat = g_h3 + BB * HH;

    __shared__ __align__(16) float As[32][68];
    __shared__ __align__(16) float Ws[32][64];

    const int tid = threadIdx.x;
    const int n0 = blockIdx.x * 64;
    const int m0 = blockIdx.y * 64;
    const int tx = tid & 15;
    const int ty = tid >> 4;

    u64 acc[4][4];
#pragma unroll
    for (int pr = 0; pr < 4; pr++)
#pragma unroll
        for (int c = 0; c < 4; c++) acc[pr][c] = splat2(bout[n0 + tx * 4 + c]);

    for (int kc = 0; kc < HH; kc += 32) {
#pragma unroll
        for (int i = 0; i < 16; i++) {
            int idx = tid + i * 128;
            int r = idx >> 5, kk = idx & 31;
            As[kk][r] = Amat[(size_t)(m0 + r) * HH + kc + kk];
        }
#pragma unroll
        for (int i = 0; i < 16; i++) {
            int idx = tid + i * 128;
            int kk = idx >> 6, n = idx & 63;
            Ws[kk][n] = Wout[(size_t)(kc + kk) * VV + n0 + n];
        }
        __syncthreads();
#pragma unroll
        for (int kk = 0; kk < 32; kk++) {
            double2 xa = *(const double2*)&As[kk][ty * 8];
            double2 xb = *(const double2*)&As[kk][ty * 8 + 4];
            float4  wf = *(const float4*)&Ws[kk][tx * 4];
            u64 xp[4] = { __double_as_longlong(xa.x), __double_as_longlong(xa.y),
                          __double_as_longlong(xb.x), __double_as_longlong(xb.y) };
            u64 w0 = splat2(wf.x), w1 = splat2(wf.y);
            u64 w2 = splat2(wf.z), w3 = splat2(wf.w);
#pragma unroll
            for (int pr = 0; pr < 4; pr++) {
                acc[pr][0] = ffma2(xp[pr], w0, acc[pr][0]);
                acc[pr][1] = ffma2(xp[pr], w1, acc[pr][1]);
                acc[pr][2] = ffma2(xp[pr], w2, acc[pr][2]);
                acc[pr][3] = ffma2(xp[pr], w3, acc[pr][3]);
            }
        }
        __syncthreads();
    }

#pragma unroll
    for (int pr = 0; pr < 4; pr++) {
        float lo[4], hi[4];
#pragma unroll
        for (int c = 0; c < 4; c++) unpack2(acc[pr][c], lo[c], hi[c]);
        int m = m0 + ty * 8 + pr * 2;
        *(float4*)&out[(size_t)m * VV + n0 + tx * 4]       = make_float4(lo[0], lo[1], lo[2], lo[3]);
        *(float4*)&out[(size_t)(m + 1) * VV + n0 + tx * 4] = make_float4(hi[0], hi[1], hi[2], hi[3]);
    }
}

// ---------------- final states ----------------
__global__ void copy_states(float* __restrict__ out) {
    int i = blockIdx.x * blockDim.x + threadIdx.x;
    if (i < BB * HH) {
        out[0 * BB * HH + i] = g_hbuf1[0][i];
        out[1 * BB * HH + i] = g_c[0][i];
        out[2 * BB * HH + i] = g_hbuf2[0][i];
        out[3 * BB * HH + i] = g_c[1][i];
        out[4 * BB * HH + i] = g_h3[(size_t)TT * BB * HH + i];
        out[5 * BB * HH + i] = g_c[2][i];
    }
}

// ---------------- launch (4 graph nodes total) ----------------
extern "C" void kernel_launch(void* const* d_in, const int* in_sizes, int n_in,
                              void* d_out, int out_size) {
    const int*   X    = (const int*)  d_in[0];
    const float* W1   = (const float*)d_in[1];
    const float* b1   = (const float*)d_in[2];
    const float* W2   = (const float*)d_in[3];
    const float* b2   = (const float*)d_in[4];
    const float* W3   = (const float*)d_in[5];
    const float* b3   = (const float*)d_in[6];
    const float* Wout = (const float*)d_in[7];
    const float* bout = (const float*)d_in[8];
    float* out = (float*)d_out;
    (void)in_sizes; (void)n_in;

    init_zero<<<(BB * HH + 255) / 256, 256>>>();
    lstm_persist<<<NBLK, NTHR>>>(X, W1, b1, W2, b2, W3, b3);

    dim3 out_grid(VV / 64, (TT * BB) / 64);
    out_gemm<<<out_grid, 128>>>(Wout, bout, out);

    long long need = (long long)TT * BB * VV + 6LL * BB * HH;
    if ((long long)out_size >= need) {
        copy_states<<<(BB * HH + 255) / 256, 256>>>(out + (size_t)TT * BB * VV);
    }
}

// round 5
// speedup vs baseline: 2.4419x; 2.4419x over previous
#include <cuda_runtime.h>
#include <cuda_bf16.h>
#include <math.h>
#include <stdint.h>

#define BB 64
#define HH 1024
#define VV 2048
#define TT 256
#define GG 4096
#define NBLK 128
#define NTHR 256

typedef unsigned long long u64;
typedef unsigned int u32;

// ---------------- device globals ----------------
// weight images: per (ntile, kchunk) 16KB tile = [hi 8KB][lo 8KB], each [64 n][64 k] bf16,
// 128B rows, SW128-swizzled.
__device__ __align__(128) unsigned char g_w0img[16u * 1024 * 1024];   // 64 nt * 16 kc
__device__ __align__(128) unsigned char g_w1img[32u * 1024 * 1024];   // 64 nt * 32 kc
__device__ __align__(128) unsigned char g_w2img[32u * 1024 * 1024];
// activation images: [parity][16 tiles * 16KB], tile = [hi 8KB][lo 8KB] of [64 m][64 k]
__device__ __align__(128) unsigned char g_img1[2][16 * 16384];
__device__ __align__(128) unsigned char g_img2[2][16 * 16384];
__device__ __align__(128) unsigned char g_img3[2][16 * 16384];
__device__ float g_c[3][BB * HH];
__device__ float g_hfin[2][BB * HH];
__device__ float g_h3[(TT + 1) * BB * HH];
__device__ float g_partial[64 * 4096];           // kh=1 partial D per ntile
__device__ unsigned g_flag[64];

__device__ unsigned g_count = 0;
__device__ volatile unsigned g_gen = 0;

__device__ __forceinline__ u32 swz(u32 off) { return off ^ ((off >> 3) & 0x70); }

__device__ __forceinline__ u32 smem_u32(const void* p) {
    u32 r;
    asm("{ .reg .u64 t; cvta.to.shared.u64 t, %1; cvt.u32.u64 %0, t; }" : "=r"(r) : "l"(p));
    return r;
}
__device__ __forceinline__ void cp16(u32 d, const void* s) {
    asm volatile("cp.async.cg.shared.global [%0], [%1], 16;" :: "r"(d), "l"(s) : "memory");
}
__device__ __forceinline__ void cp_commit() { asm volatile("cp.async.commit_group;" ::: "memory"); }
__device__ __forceinline__ void cp_wait1()  { asm volatile("cp.async.wait_group 1;" ::: "memory"); }
__device__ __forceinline__ void cp_wait0()  { asm volatile("cp.async.wait_group 0;" ::: "memory"); }

__device__ __forceinline__ void ldm4(u32 addr, u32* r) {
    asm volatile("ldmatrix.sync.aligned.m8n8.x4.shared.b16 {%0,%1,%2,%3}, [%4];"
                 : "=r"(r[0]), "=r"(r[1]), "=r"(r[2]), "=r"(r[3]) : "r"(addr));
}
__device__ __forceinline__ u32 ldm_addr(u32 tilebase, int rbase, int kq, int lane) {
    int row  = rbase + (lane & 7) + ((lane >> 3) & 1) * 8;
    int colb = kq * 32 + ((lane >> 4) & 1) * 16;
    return tilebase + swz((u32)(row * 128 + colb));
}
__device__ __forceinline__ void mma16816(float* d, const u32* a, u32 b0, u32 b1) {
    asm volatile("mma.sync.aligned.m16n8k16.row.col.f32.bf16.bf16.f32 "
                 "{%0,%1,%2,%3},{%4,%5,%6,%7},{%8,%9},{%0,%1,%2,%3};"
                 : "+f"(d[0]), "+f"(d[1]), "+f"(d[2]), "+f"(d[3])
                 : "r"(a[0]), "r"(a[1]), "r"(a[2]), "r"(a[3]), "r"(b0), "r"(b1));
}

// ---------------- grid barrier ----------------
__device__ __forceinline__ void gbar() {
    __syncthreads();
    if (threadIdx.x == 0) {
        unsigned gen = g_gen;
        __threadfence();
        unsigned a = atomicAdd(&g_count, 1);
        if (a == NBLK - 1) {
            atomicExch(&g_count, 0);
            __threadfence();
            g_gen = gen + 1;
        } else {
            while (g_gen == gen) { __nanosleep(32); }
            __threadfence();
        }
    }
    __syncthreads();
}

// ---------------- init ----------------
__global__ void init_zero() {
    int i = blockIdx.x * blockDim.x + threadIdx.x;
    if (i < BB * HH) {
        g_c[0][i] = 0.f; g_c[1][i] = 0.f; g_c[2][i] = 0.f;
        g_h3[i] = 0.f;
    }
    if (i < 64) g_flag[i] = 0u;
    int n32 = 16 * 16384 / 4;
    for (int j = i; j < n32; j += gridDim.x * blockDim.x) {
        ((u32*)g_img1[0])[j] = 0u;
        ((u32*)g_img2[0])[j] = 0u;
        ((u32*)g_img3[0])[j] = 0u;
    }
}

// ---------------- weight conversion ----------------
__global__ void wconv(const float* __restrict__ W1, const float* __restrict__ W2,
                      const float* __restrict__ W3) {
    int l = blockIdx.y;
    size_t idx = (size_t)blockIdx.x * blockDim.x + threadIdx.x;
    int K = (l == 0) ? HH : 2 * HH;
    if (idx >= (size_t)K * GG) return;
    int k = (int)(idx >> 12);
    int n = (int)(idx & 4095);
    float w;
    if (l == 0)      w = W1[(size_t)(VV + k) * GG + n];
    else if (l == 1) w = W2[idx];
    else             w = W3[idx];
    __nv_bfloat16 hi = __float2bfloat16(w);
    __nv_bfloat16 lo = __float2bfloat16(w - __bfloat162float(hi));
    int g = n >> 10, u = n & 1023;
    int nt = u >> 4, jj = u & 15;
    int nc = g * 16 + jj;                 // row in [n][k] tile
    int nch = K >> 6;
    size_t base = ((size_t)nt * nch + (k >> 6)) * 16384;
    u32 off = swz((u32)(nc * 128 + (k & 63) * 2));
    unsigned char* img = (l == 0) ? g_w0img : (l == 1) ? g_w1img : g_w2img;
    *(__nv_bfloat16*)(img + base + off)        = hi;
    *(__nv_bfloat16*)(img + base + 8192 + off) = lo;
}

// ---------------- persistent mma.sync LSTM ----------------
// 128 blocks = 64 ntiles x 2 khalf. Block tile: M=64 x N=64 (16 j x 4 gates), K-half.
// 8 warps: mt = wid>>1 (m tile of 16), nh = wid&1 (32-col half -> 4 ntiles of 8).
__global__ void __launch_bounds__(NTHR, 1) lstm_persist(
    const int*   __restrict__ X,
    const float* __restrict__ W1,
    const float* __restrict__ b1, const float* __restrict__ b2, const float* __restrict__ b3)
{
    extern __shared__ unsigned char dynsm[];
    u32 raw = smem_u32(dynsm);
    u32 sb = (raw + 127u) & ~127u;
    float* Sm = (float*)(dynsm + (sb - raw) + 65536);   // [64 c][65 m] f32

    const int tid  = threadIdx.x;
    const int wid  = tid >> 5;
    const int lane = tid & 31;
    const int bid  = blockIdx.x;
    const int nt   = bid >> 1;
    const int kh   = bid & 1;
    const int j0   = nt * 16;
    const int mt   = wid >> 1;
    const int nh   = wid & 1;
    const int m0   = mt * 16;
    const int nb   = nh * 32;

    for (int t = 0; t < TT; t++) {
        for (int layer = 0; layer < 3; layer++) {
            const int ls = t * 3 + layer;
            int nch;                                   // chunks in this block's K-half
            const unsigned char* wimg;
            const unsigned char* aimg;
            int abase;
            if (layer == 0) {
                nch = 8; wimg = g_w0img;
                aimg = g_img1[t & 1]; abase = kh * 8;
            } else if (layer == 1) {
                nch = 16; wimg = g_w1img;
                aimg = kh ? g_img2[t & 1] : g_img1[(t + 1) & 1]; abase = 0;
            } else {
                nch = 16; wimg = g_w2img;
                aimg = kh ? g_img3[t & 1] : g_img2[(t + 1) & 1]; abase = 0;
            }
            const unsigned char* wbase = wimg + ((size_t)nt * (2 * nch) + (size_t)kh * nch) * 16384;

            float acc[4][4];
#pragma unroll
            for (int i = 0; i < 4; i++)
#pragma unroll
                for (int q = 0; q < 4; q++) acc[i][q] = 0.f;

            // stage chunk 0
            {
                const unsigned char* at = aimg + (size_t)(abase + 0) * 16384;
                const unsigned char* wt = wbase;
#pragma unroll
                for (int i = 0; i < 4; i++) {
                    cp16(sb + i * 4096 + tid * 16,         at + i * 4096 + tid * 16);
                    cp16(sb + 16384 + i * 4096 + tid * 16, wt + i * 4096 + tid * 16);
                }
                cp_commit();
            }

            for (int c = 0; c < nch; c++) {
                const bool more = (c + 1 < nch);
                if (more) {
                    int buf = (c + 1) & 1;
                    const unsigned char* at = aimg + (size_t)(abase + c + 1) * 16384;
                    const unsigned char* wt = wbase + (size_t)(c + 1) * 16384;
#pragma unroll
                    for (int i = 0; i < 4; i++) {
                        cp16(sb + buf * 32768 + i * 4096 + tid * 16,         at + i * 4096 + tid * 16);
                        cp16(sb + buf * 32768 + 16384 + i * 4096 + tid * 16, wt + i * 4096 + tid * 16);
                    }
                    cp_commit();
                    cp_wait1();
                } else {
                    cp_wait0();
                }
                __syncthreads();

                u32 Ahi = sb + (c & 1) * 32768;
                u32 Alo = Ahi + 8192;
                u32 Whi = Ahi + 16384;
                u32 Wlo = Ahi + 24576;
#pragma unroll
                for (int kq = 0; kq < 4; kq++) {
                    u32 ah[4], al[4], bh0[4], bh1[4], bl0[4], bl1[4];
                    ldm4(ldm_addr(Ahi, m0, kq, lane), ah);
                    ldm4(ldm_addr(Alo, m0, kq, lane), al);
                    ldm4(ldm_addr(Whi, nb, kq, lane), bh0);
                    ldm4(ldm_addr(Whi, nb + 16, kq, lane), bh1);
                    ldm4(ldm_addr(Wlo, nb, kq, lane), bl0);
                    ldm4(ldm_addr(Wlo, nb + 16, kq, lane), bl1);
                    // ntile0: rows n0-7 -> {r0,r2}; ntile1: {r1,r3}; ntiles 2,3 from *1 frags
                    mma16816(acc[0], ah, bh0[0], bh0[2]);
                    mma16816(acc[1], ah, bh0[1], bh0[3]);
                    mma16816(acc[2], ah, bh1[0], bh1[2]);
                    mma16816(acc[3], ah, bh1[1], bh1[3]);
                    mma16816(acc[0], ah, bl0[0], bl0[2]);
                    mma16816(acc[1], ah, bl0[1], bl0[3]);
                    mma16816(acc[2], ah, bl1[0], bl1[2]);
                    mma16816(acc[3], ah, bl1[1], bl1[3]);
                    mma16816(acc[0], al, bh0[0], bh0[2]);
                    mma16816(acc[1], al, bh0[1], bh0[3]);
                    mma16816(acc[2], al, bh1[0], bh1[2]);
                    mma16816(acc[3], al, bh1[1], bh1[3]);
                }
                __syncthreads();
            }

            // dump accumulators to Sm[c][m]
            {
                int gid = lane >> 2, tig = lane & 3;
                int mrow = m0 + gid;
#pragma unroll
                for (int nti = 0; nti < 4; nti++) {
                    int cc = nb + nti * 8 + tig * 2;
                    Sm[cc * 65 + mrow]           = acc[nti][0];
                    Sm[(cc + 1) * 65 + mrow]     = acc[nti][1];
                    Sm[cc * 65 + mrow + 8]       = acc[nti][2];
                    Sm[(cc + 1) * 65 + mrow + 8] = acc[nti][3];
                }
            }
            __syncthreads();

            if (kh == 1) {
                // export partial, signal
                float* pp = g_partial + nt * 4096;
#pragma unroll
                for (int i = 0; i < 16; i++) {
                    int e = tid + i * 256;
                    pp[e] = Sm[(e >> 6) * 65 + (e & 63)];
                }
                __threadfence();
                __syncthreads();
                if (tid == 0) atomicExch(&g_flag[nt], (unsigned)(ls + 1));
            } else {
                // wait for partner, reduce, gates
                if (tid == 0) {
                    while (((volatile unsigned*)g_flag)[nt] != (unsigned)(ls + 1)) __nanosleep(16);
                    __threadfence();
                }
                __syncthreads();
                const float* pp = g_partial + nt * 4096;
#pragma unroll
                for (int i = 0; i < 16; i++) {
                    int e = tid + i * 256;
                    Sm[(e >> 6) * 65 + (e & 63)] += pp[e];
                }
                __syncthreads();

                const float* bias = (layer == 0) ? b1 : (layer == 1) ? b2 : b3;
                float* cbuf = g_c[layer];
                unsigned char* imgout = (layer == 0) ? g_img1[(t + 1) & 1]
                                      : (layer == 1) ? g_img2[(t + 1) & 1]
                                                     : g_img3[(t + 1) & 1];
#pragma unroll
                for (int i = 0; i < 4; i++) {
                    int e  = tid + i * 256;     // 0..1023
                    int m  = e & 63;
                    int jj = e >> 6;
                    int jg = j0 + jj;
                    float f  = Sm[jj * 65 + m]        + bias[jg];
                    float ig = Sm[(16 + jj) * 65 + m] + bias[HH + jg];
                    float og = Sm[(32 + jj) * 65 + m] + bias[2 * HH + jg];
                    float ct = Sm[(48 + jj) * 65 + m] + bias[3 * HH + jg];
                    if (layer == 0) {
                        int xid = X[m * TT + t];
                        const float* wrow = W1 + (size_t)xid * GG + jg;
                        f  += wrow[0];
                        ig += wrow[HH];
                        og += wrow[2 * HH];
                        ct += wrow[3 * HH];
                    }
                    int cidx = m * HH + jg;
                    float cv = cbuf[cidx];
                    float sf = 1.f / (1.f + __expf(-f));
                    float si = 1.f / (1.f + __expf(-ig));
                    float so = 1.f / (1.f + __expf(-og));
                    float cn = sf * cv + si * tanhf(ct);
                    float hn = so * tanhf(cn);
                    cbuf[cidx] = cn;

                    __nv_bfloat16 hi = __float2bfloat16(hn);
                    __nv_bfloat16 lo = __float2bfloat16(hn - __bfloat162float(hi));
                    unsigned char* cb = imgout + (size_t)(jg >> 6) * 16384;
                    u32 off = swz((u32)(m * 128 + (jg & 63) * 2));
                    *(__nv_bfloat16*)(cb + off)        = hi;
                    *(__nv_bfloat16*)(cb + 8192 + off) = lo;

                    if (layer == 2) g_h3[(size_t)(t + 1) * BB * HH + cidx] = hn;
                    else if (t == TT - 1) g_hfin[layer][cidx] = hn;
                }
            }

            gbar();
        }
    }
}

// ---------------- out GEMM (f32x2 SIMT, known-good) ----------------
__device__ __forceinline__ u64 ffma2(u64 a, u64 b, u64 c) {
    u64 d; asm("fma.rn.f32x2 %0, %1, %2, %3;" : "=l"(d) : "l"(a), "l"(b), "l"(c)); return d;
}
__device__ __forceinline__ u64 splat2(float w) {
    u64 d; asm("mov.b64 %0, {%1, %1};" : "=l"(d) : "f"(w)); return d;
}
__device__ __forceinline__ void unpack2(u64 v, float& lo, float& hi) {
    asm("mov.b64 {%0, %1}, %2;" : "=f"(lo), "=f"(hi) : "l"(v));
}

__global__ void __launch_bounds__(128) out_gemm(
    const float* __restrict__ Wout, const float* __restrict__ bout, float* __restrict__ out)
{
    const float* Amat = g_h3 + BB * HH;
    __shared__ __align__(16) float As[32][68];
    __shared__ __align__(16) float Ws[32][64];
    const int tid = threadIdx.x;
    const int n0 = blockIdx.x * 64;
    const int m0 = blockIdx.y * 64;
    const int tx = tid & 15;
    const int ty = tid >> 4;

    u64 acc[4][4];
#pragma unroll
    for (int pr = 0; pr < 4; pr++)
#pragma unroll
        for (int c = 0; c < 4; c++) acc[pr][c] = splat2(bout[n0 + tx * 4 + c]);

    for (int kc = 0; kc < HH; kc += 32) {
#pragma unroll
        for (int i = 0; i < 16; i++) {
            int idx = tid + i * 128;
            int r = idx >> 5, kk = idx & 31;
            As[kk][r] = Amat[(size_t)(m0 + r) * HH + kc + kk];
        }
#pragma unroll
        for (int i = 0; i < 16; i++) {
            int idx = tid + i * 128;
            int kk = idx >> 6, n = idx & 63;
            Ws[kk][n] = Wout[(size_t)(kc + kk) * VV + n0 + n];
        }
        __syncthreads();
#pragma unroll
        for (int kk = 0; kk < 32; kk++) {
            double2 xa = *(const double2*)&As[kk][ty * 8];
            double2 xb = *(const double2*)&As[kk][ty * 8 + 4];
            float4  wf = *(const float4*)&Ws[kk][tx * 4];
            u64 xp[4] = { __double_as_longlong(xa.x), __double_as_longlong(xa.y),
                          __double_as_longlong(xb.x), __double_as_longlong(xb.y) };
            u64 w0 = splat2(wf.x), w1 = splat2(wf.y), w2 = splat2(wf.z), w3 = splat2(wf.w);
#pragma unroll
            for (int pr = 0; pr < 4; pr++) {
                acc[pr][0] = ffma2(xp[pr], w0, acc[pr][0]);
                acc[pr][1] = ffma2(xp[pr], w1, acc[pr][1]);
                acc[pr][2] = ffma2(xp[pr], w2, acc[pr][2]);
                acc[pr][3] = ffma2(xp[pr], w3, acc[pr][3]);
            }
        }
        __syncthreads();
    }
#pragma unroll
    for (int pr = 0; pr < 4; pr++) {
        float lo[4], hi[4];
#pragma unroll
        for (int c = 0; c < 4; c++) unpack2(acc[pr][c], lo[c], hi[c]);
        int m = m0 + ty * 8 + pr * 2;
        *(float4*)&out[(size_t)m * VV + n0 + tx * 4]       = make_float4(lo[0], lo[1], lo[2], lo[3]);
        *(float4*)&out[(size_t)(m + 1) * VV + n0 + tx * 4] = make_float4(hi[0], hi[1], hi[2], hi[3]);
    }
}

__global__ void copy_states(float* __restrict__ out) {
    int i = blockIdx.x * blockDim.x + threadIdx.x;
    if (i < BB * HH) {
        out[0 * BB * HH + i] = g_hfin[0][i];
        out[1 * BB * HH + i] = g_c[0][i];
        out[2 * BB * HH + i] = g_hfin[1][i];
        out[3 * BB * HH + i] = g_c[1][i];
        out[4 * BB * HH + i] = g_h3[(size_t)TT * BB * HH + i];
        out[5 * BB * HH + i] = g_c[2][i];
    }
}

// ---------------- launch ----------------
extern "C" void kernel_launch(void* const* d_in, const int* in_sizes, int n_in,
                              void* d_out, int out_size) {
    const int*   X    = (const int*)  d_in[0];
    const float* W1   = (const float*)d_in[1];
    const float* b1   = (const float*)d_in[2];
    const float* W2   = (const float*)d_in[3];
    const float* b2   = (const float*)d_in[4];
    const float* W3   = (const float*)d_in[5];
    const float* b3   = (const float*)d_in[6];
    const float* Wout = (const float*)d_in[7];
    const float* bout = (const float*)d_in[8];
    float* out = (float*)d_out;
    (void)in_sizes; (void)n_in;

    static int attr_done = 0;
    if (!attr_done) {
        cudaFuncSetAttribute(lstm_persist, cudaFuncAttributeMaxDynamicSharedMemorySize, 84096);
        attr_done = 1;
    }

    init_zero<<<256, 256>>>();

    dim3 wgrid((2u * HH * GG + 255) / 256, 3);
    wconv<<<wgrid, 256>>>(W1, W2, W3);

    lstm_persist<<<NBLK, NTHR, 84096>>>(X, W1, b1, b2, b3);

    dim3 out_grid(VV / 64, (TT * BB) / 64);
    out_gemm<<<out_grid, 128>>>(Wout, bout, out);

    long long need = (long long)TT * BB * VV + 6LL * BB * HH;
    if ((long long)out_size >= need) {
        copy_states<<<(BB * HH + 255) / 256, 256>>>(out + (size_t)TT * BB * VV);
    }
}

// round 6
// speedup vs baseline: 2.6925x; 1.1027x over previous
#include <cuda_runtime.h>
#include <cuda_bf16.h>
#include <math.h>
#include <stdint.h>

#define BB 64
#define HH 1024
#define VV 2048
#define TT 256
#define GG 4096
#define NBLK 128
#define NTHR 256

typedef unsigned long long u64;
typedef unsigned int u32;

// ---------------- device globals ----------------
__device__ __align__(128) unsigned char g_w0img[16u * 1024 * 1024];
__device__ __align__(128) unsigned char g_w1img[32u * 1024 * 1024];
__device__ __align__(128) unsigned char g_w2img[32u * 1024 * 1024];
__device__ __align__(128) unsigned char g_img1[2][16 * 16384];
__device__ __align__(128) unsigned char g_img2[2][16 * 16384];
__device__ __align__(128) unsigned char g_img3[2][16 * 16384];
__device__ float g_c[3][BB * HH];
__device__ float g_hfin[2][BB * HH];
__device__ float g_h3[(TT + 1) * BB * HH];
__device__ float g_part[3 * 64 * 4096];          // per-layer partials
__device__ unsigned g_flag[3 * 64];

__device__ unsigned g_count = 0;
__device__ volatile unsigned g_gen = 0;

__device__ __forceinline__ u32 swz(u32 off) { return off ^ ((off >> 3) & 0x70); }

__device__ __forceinline__ u32 smem_u32(const void* p) {
    u32 r;
    asm("{ .reg .u64 t; cvta.to.shared.u64 t, %1; cvt.u32.u64 %0, t; }" : "=r"(r) : "l"(p));
    return r;
}
__device__ __forceinline__ void cp16(u32 d, const void* s) {
    asm volatile("cp.async.cg.shared.global [%0], [%1], 16;" :: "r"(d), "l"(s) : "memory");
}
__device__ __forceinline__ void cp_commit() { asm volatile("cp.async.commit_group;" ::: "memory"); }
__device__ __forceinline__ void cp_wait1()  { asm volatile("cp.async.wait_group 1;" ::: "memory"); }
__device__ __forceinline__ void cp_wait0()  { asm volatile("cp.async.wait_group 0;" ::: "memory"); }

__device__ __forceinline__ void ldm4(u32 addr, u32* r) {
    asm volatile("ldmatrix.sync.aligned.m8n8.x4.shared.b16 {%0,%1,%2,%3}, [%4];"
                 : "=r"(r[0]), "=r"(r[1]), "=r"(r[2]), "=r"(r[3]) : "r"(addr));
}
__device__ __forceinline__ u32 ldm_addr(u32 tilebase, int rbase, int kq, int lane) {
    int row  = rbase + (lane & 7) + ((lane >> 3) & 1) * 8;
    int colb = kq * 32 + ((lane >> 4) & 1) * 16;
    return tilebase + swz((u32)(row * 128 + colb));
}
__device__ __forceinline__ void mma16816(float* d, const u32* a, u32 b0, u32 b1) {
    asm volatile("mma.sync.aligned.m16n8k16.row.col.f32.bf16.bf16.f32 "
                 "{%0,%1,%2,%3},{%4,%5,%6,%7},{%8,%9},{%0,%1,%2,%3};"
                 : "+f"(d[0]), "+f"(d[1]), "+f"(d[2]), "+f"(d[3])
                 : "r"(a[0]), "r"(a[1]), "r"(a[2]), "r"(a[3]), "r"(b0), "r"(b1));
}

// ---------------- grid barrier ----------------
__device__ __forceinline__ void gbar() {
    __syncthreads();
    if (threadIdx.x == 0) {
        unsigned gen = g_gen;
        __threadfence();
        unsigned a = atomicAdd(&g_count, 1);
        if (a == NBLK - 1) {
            atomicExch(&g_count, 0);
            __threadfence();
            g_gen = gen + 1;
        } else {
            while (g_gen == gen) { __nanosleep(32); }
            __threadfence();
        }
    }
    __syncthreads();
}

// ---------------- init ----------------
__global__ void init_zero() {
    int i = blockIdx.x * blockDim.x + threadIdx.x;
    if (i < BB * HH) {
        g_c[0][i] = 0.f; g_c[1][i] = 0.f; g_c[2][i] = 0.f;
        g_h3[i] = 0.f;
    }
    if (i < 3 * 64) g_flag[i] = 0u;
    int n32 = 16 * 16384 / 4;
    for (int j = i; j < n32; j += gridDim.x * blockDim.x) {
        ((u32*)g_img1[0])[j] = 0u;
        ((u32*)g_img2[0])[j] = 0u;
        ((u32*)g_img3[0])[j] = 0u;
    }
}

// ---------------- weight conversion ----------------
__global__ void wconv(const float* __restrict__ W1, const float* __restrict__ W2,
                      const float* __restrict__ W3) {
    int l = blockIdx.y;
    size_t idx = (size_t)blockIdx.x * blockDim.x + threadIdx.x;
    int K = (l == 0) ? HH : 2 * HH;
    if (idx >= (size_t)K * GG) return;
    int k = (int)(idx >> 12);
    int n = (int)(idx & 4095);
    float w;
    if (l == 0)      w = W1[(size_t)(VV + k) * GG + n];
    else if (l == 1) w = W2[idx];
    else             w = W3[idx];
    __nv_bfloat16 hi = __float2bfloat16(w);
    __nv_bfloat16 lo = __float2bfloat16(w - __bfloat162float(hi));
    int g = n >> 10, u = n & 1023;
    int nt = u >> 4, jj = u & 15;
    int nc = g * 16 + jj;
    int nch = K >> 6;
    size_t base = ((size_t)nt * nch + (k >> 6)) * 16384;
    u32 off = swz((u32)(nc * 128 + (k & 63) * 2));
    unsigned char* img = (l == 0) ? g_w0img : (l == 1) ? g_w1img : g_w2img;
    *(__nv_bfloat16*)(img + base + off)        = hi;
    *(__nv_bfloat16*)(img + base + 8192 + off) = lo;
}

// ---------------- layer params ----------------
struct LayerP {
    int nch;
    const unsigned char* wbase;
    const unsigned char* aimg;
    int abase;
};
__device__ __forceinline__ LayerP layer_params(int l, int t, int nt, int kh) {
    LayerP p;
    if (l == 0) {
        p.nch = 8;
        p.wbase = g_w0img + ((size_t)nt * 16 + (size_t)kh * 8) * 16384;
        p.aimg = g_img1[t & 1]; p.abase = kh * 8;
    } else if (l == 1) {
        p.nch = 16;
        p.wbase = g_w1img + ((size_t)nt * 32 + (size_t)kh * 16) * 16384;
        p.aimg = kh ? g_img2[t & 1] : g_img1[(t + 1) & 1]; p.abase = 0;
    } else {
        p.nch = 16;
        p.wbase = g_w2img + ((size_t)nt * 32 + (size_t)kh * 16) * 16384;
        p.aimg = kh ? g_img3[t & 1] : g_img2[(t + 1) & 1]; p.abase = 0;
    }
    return p;
}

// ---------------- persistent wavefront LSTM ----------------
__global__ void __launch_bounds__(NTHR, 1) lstm_persist(
    const int*   __restrict__ X,
    const float* __restrict__ W1,
    const float* __restrict__ b1, const float* __restrict__ b2, const float* __restrict__ b3)
{
    extern __shared__ unsigned char dynsm[];
    u32 raw = smem_u32(dynsm);
    u32 sb = (raw + 127u) & ~127u;
    float* Sm = (float*)(dynsm + (sb - raw) + 65536);   // [64 c][65 m]

    const int tid  = threadIdx.x;
    const int wid  = tid >> 5;
    const int lane = tid & 31;
    const int bid  = blockIdx.x;
    const int nt   = bid >> 1;
    const int kh   = bid & 1;
    const int j0   = nt * 16;
    const int mt   = wid >> 1;
    const int nh   = wid & 1;
    const int m0   = mt * 16;
    const int nb   = nh * 32;

    for (int w = 0; w < TT + 2; w++) {
        bool staged = false;
        for (int l = 0; l < 3; l++) {
            const int t = w - l;
            if (t < 0 || t >= TT) continue;

            LayerP P = layer_params(l, t, nt, kh);

            if (!staged) {
                const unsigned char* at = P.aimg + (size_t)(P.abase) * 16384;
                const unsigned char* wt = P.wbase;
#pragma unroll
                for (int i = 0; i < 4; i++) {
                    cp16(sb + i * 4096 + tid * 16,         at + i * 4096 + tid * 16);
                    cp16(sb + 16384 + i * 4096 + tid * 16, wt + i * 4096 + tid * 16);
                }
                cp_commit();
            }

            float acc[4][4];
#pragma unroll
            for (int i = 0; i < 4; i++)
#pragma unroll
                for (int q = 0; q < 4; q++) acc[i][q] = 0.f;

            for (int c = 0; c < P.nch; c++) {
                const bool more = (c + 1 < P.nch);
                if (more) {
                    int buf = (c + 1) & 1;
                    const unsigned char* at = P.aimg + (size_t)(P.abase + c + 1) * 16384;
                    const unsigned char* wt = P.wbase + (size_t)(c + 1) * 16384;
#pragma unroll
                    for (int i = 0; i < 4; i++) {
                        cp16(sb + buf * 32768 + i * 4096 + tid * 16,         at + i * 4096 + tid * 16);
                        cp16(sb + buf * 32768 + 16384 + i * 4096 + tid * 16, wt + i * 4096 + tid * 16);
                    }
                    cp_commit();
                    cp_wait1();
                } else {
                    cp_wait0();
                }
                __syncthreads();

                u32 Ahi = sb + (c & 1) * 32768;
                u32 Alo = Ahi + 8192;
                u32 Whi = Ahi + 16384;
                u32 Wlo = Ahi + 24576;
#pragma unroll
                for (int kq = 0; kq < 4; kq++) {
                    u32 ah[4], al[4], bh0[4], bh1[4], bl0[4], bl1[4];
                    ldm4(ldm_addr(Ahi, m0, kq, lane), ah);
                    ldm4(ldm_addr(Alo, m0, kq, lane), al);
                    ldm4(ldm_addr(Whi, nb, kq, lane), bh0);
                    ldm4(ldm_addr(Whi, nb + 16, kq, lane), bh1);
                    ldm4(ldm_addr(Wlo, nb, kq, lane), bl0);
                    ldm4(ldm_addr(Wlo, nb + 16, kq, lane), bl1);
                    mma16816(acc[0], ah, bh0[0], bh0[2]);
                    mma16816(acc[1], ah, bh0[1], bh0[3]);
                    mma16816(acc[2], ah, bh1[0], bh1[2]);
                    mma16816(acc[3], ah, bh1[1], bh1[3]);
                    mma16816(acc[0], ah, bl0[0], bl0[2]);
                    mma16816(acc[1], ah, bl0[1], bl0[3]);
                    mma16816(acc[2], ah, bl1[0], bl1[2]);
                    mma16816(acc[3], ah, bl1[1], bl1[3]);
                    mma16816(acc[0], al, bh0[0], bh0[2]);
                    mma16816(acc[1], al, bh0[1], bh0[3]);
                    mma16816(acc[2], al, bh1[0], bh1[2]);
                    mma16816(acc[3], al, bh1[1], bh1[3]);
                }
                __syncthreads();
            }

            // ---- prefetch chunk 0 of next layer in this wave (hides refill) ----
            staged = false;
            if (l < 2) {
                int t2 = w - (l + 1);
                if (t2 >= 0 && t2 < TT) {
                    LayerP Q = layer_params(l + 1, t2, nt, kh);
                    const unsigned char* at = Q.aimg + (size_t)(Q.abase) * 16384;
                    const unsigned char* wt = Q.wbase;
#pragma unroll
                    for (int i = 0; i < 4; i++) {
                        cp16(sb + i * 4096 + tid * 16,         at + i * 4096 + tid * 16);
                        cp16(sb + 16384 + i * 4096 + tid * 16, wt + i * 4096 + tid * 16);
                    }
                    cp_commit();
                    staged = true;
                }
            }

            // ---- epilogue: K-half exchange + gates ----
            const int owner = (l == 1) ? 1 : 0;
            float* pbase = g_part + ((size_t)l * 64 + nt) * 4096;
            unsigned* flag = &g_flag[l * 64 + nt];

            if (kh != owner) {
                // producer: dump accumulators straight from registers (L2-coherent)
                float4* pp4 = (float4*)pbase;
#pragma unroll
                for (int nti = 0; nti < 4; nti++) {
                    float4 v = make_float4(acc[nti][0], acc[nti][1], acc[nti][2], acc[nti][3]);
                    __stcg(&pp4[tid * 4 + nti], v);
                }
                __threadfence();
                __syncthreads();
                if (tid == 0) atomicExch(flag, (unsigned)(t + 1));
            } else {
                if (tid == 0) {
                    while (*(volatile unsigned*)flag != (unsigned)(t + 1)) __nanosleep(16);
                    __threadfence();
                }
                __syncthreads();
                const float4* pp4 = (const float4*)pbase;
#pragma unroll
                for (int nti = 0; nti < 4; nti++) {
                    float4 v = __ldcg(&pp4[tid * 4 + nti]);
                    acc[nti][0] += v.x; acc[nti][1] += v.y;
                    acc[nti][2] += v.z; acc[nti][3] += v.w;
                }
                // dump full result to Sm
                {
                    int gid = lane >> 2, tig = lane & 3;
                    int mrow = m0 + gid;
#pragma unroll
                    for (int nti = 0; nti < 4; nti++) {
                        int cc = nb + nti * 8 + tig * 2;
                        Sm[cc * 65 + mrow]           = acc[nti][0];
                        Sm[(cc + 1) * 65 + mrow]     = acc[nti][1];
                        Sm[cc * 65 + mrow + 8]       = acc[nti][2];
                        Sm[(cc + 1) * 65 + mrow + 8] = acc[nti][3];
                    }
                }
                __syncthreads();

                const float* bias = (l == 0) ? b1 : (l == 1) ? b2 : b3;
                float* cbuf = g_c[l];
                unsigned char* imgout = (l == 0) ? g_img1[(t + 1) & 1]
                                      : (l == 1) ? g_img2[(t + 1) & 1]
                                                 : g_img3[(t + 1) & 1];
#pragma unroll
                for (int i = 0; i < 4; i++) {
                    int e  = tid + i * 256;
                    int m  = e & 63;
                    int jj = e >> 6;
                    int jg = j0 + jj;
                    float f  = Sm[jj * 65 + m]        + bias[jg];
                    float ig = Sm[(16 + jj) * 65 + m] + bias[HH + jg];
                    float og = Sm[(32 + jj) * 65 + m] + bias[2 * HH + jg];
                    float ct = Sm[(48 + jj) * 65 + m] + bias[3 * HH + jg];
                    if (l == 0) {
                        int xid = X[m * TT + t];
                        const float* wrow = W1 + (size_t)xid * GG + jg;
                        f  += wrow[0];
                        ig += wrow[HH];
                        og += wrow[2 * HH];
                        ct += wrow[3 * HH];
                    }
                    int cidx = m * HH + jg;
                    float cv = cbuf[cidx];
                    float sf = 1.f / (1.f + __expf(-f));
                    float si = 1.f / (1.f + __expf(-ig));
                    float so = 1.f / (1.f + __expf(-og));
                    float cn = sf * cv + si * tanhf(ct);
                    float hn = so * tanhf(cn);
                    cbuf[cidx] = cn;

                    __nv_bfloat16 hi = __float2bfloat16(hn);
                    __nv_bfloat16 lo = __float2bfloat16(hn - __bfloat162float(hi));
                    unsigned char* cb = imgout + (size_t)(jg >> 6) * 16384;
                    u32 off = swz((u32)(m * 128 + (jg & 63) * 2));
                    *(__nv_bfloat16*)(cb + off)        = hi;
                    *(__nv_bfloat16*)(cb + 8192 + off) = lo;

                    if (l == 2) g_h3[(size_t)(t + 1) * BB * HH + cidx] = hn;
                    else if (t == TT - 1) g_hfin[l][cidx] = hn;
                }
            }
        }
        gbar();   // one barrier per wave
    }
}

// ---------------- out GEMM (f32x2 SIMT) ----------------
__device__ __forceinline__ u64 ffma2(u64 a, u64 b, u64 c) {
    u64 d; asm("fma.rn.f32x2 %0, %1, %2, %3;" : "=l"(d) : "l"(a), "l"(b), "l"(c)); return d;
}
__device__ __forceinline__ u64 splat2(float w) {
    u64 d; asm("mov.b64 %0, {%1, %1};" : "=l"(d) : "f"(w)); return d;
}
__device__ __forceinline__ void unpack2(u64 v, float& lo, float& hi) {
    asm("mov.b64 {%0, %1}, %2;" : "=f"(lo), "=f"(hi) : "l"(v));
}

__global__ void __launch_bounds__(128) out_gemm(
    const float* __restrict__ Wout, const float* __restrict__ bout, float* __restrict__ out)
{
    const float* Amat = g_h3 + BB * HH;
    __shared__ __align__(16) float As[32][68];
    __shared__ __align__(16) float Ws[32][64];
    const int tid = threadIdx.x;
    const int n0 = blockIdx.x * 64;
    const int m0 = blockIdx.y * 64;
    const int tx = tid & 15;
    const int ty = tid >> 4;

    u64 acc[4][4];
#pragma unroll
    for (int pr = 0; pr < 4; pr++)
#pragma unroll
        for (int c = 0; c < 4; c++) acc[pr][c] = splat2(bout[n0 + tx * 4 + c]);

    for (int kc = 0; kc < HH; kc += 32) {
#pragma unroll
        for (int i = 0; i < 16; i++) {
            int idx = tid + i * 128;
            int r = idx >> 5, kk = idx & 31;
            As[kk][r] = Amat[(size_t)(m0 + r) * HH + kc + kk];
        }
#pragma unroll
        for (int i = 0; i < 16; i++) {
            int idx = tid + i * 128;
            int kk = idx >> 6, n = idx & 63;
            Ws[kk][n] = Wout[(size_t)(kc + kk) * VV + n0 + n];
        }
        __syncthreads();
#pragma unroll
        for (int kk = 0; kk < 32; kk++) {
            double2 xa = *(const double2*)&As[kk][ty * 8];
            double2 xb = *(const double2*)&As[kk][ty * 8 + 4];
            float4  wf = *(const float4*)&Ws[kk][tx * 4];
            u64 xp[4] = { __double_as_longlong(xa.x), __double_as_longlong(xa.y),
                          __double_as_longlong(xb.x), __double_as_longlong(xb.y) };
            u64 w0 = splat2(wf.x), w1 = splat2(wf.y), w2 = splat2(wf.z), w3 = splat2(wf.w);
#pragma unroll
            for (int pr = 0; pr < 4; pr++) {
                acc[pr][0] = ffma2(xp[pr], w0, acc[pr][0]);
                acc[pr][1] = ffma2(xp[pr], w1, acc[pr][1]);
                acc[pr][2] = ffma2(xp[pr], w2, acc[pr][2]);
                acc[pr][3] = ffma2(xp[pr], w3, acc[pr][3]);
            }
        }
        __syncthreads();
    }
#pragma unroll
    for (int pr = 0; pr < 4; pr++) {
        float lo[4], hi[4];
#pragma unroll
        for (int c = 0; c < 4; c++) unpack2(acc[pr][c], lo[c], hi[c]);
        int m = m0 + ty * 8 + pr * 2;
        *(float4*)&out[(size_t)m * VV + n0 + tx * 4]       = make_float4(lo[0], lo[1], lo[2], lo[3]);
        *(float4*)&out[(size_t)(m + 1) * VV + n0 + tx * 4] = make_float4(hi[0], hi[1], hi[2], hi[3]);
    }
}

__global__ void copy_states(float* __restrict__ out) {
    int i = blockIdx.x * blockDim.x + threadIdx.x;
    if (i < BB * HH) {
        out[0 * BB * HH + i] = g_hfin[0][i];
        out[1 * BB * HH + i] = g_c[0][i];
        out[2 * BB * HH + i] = g_hfin[1][i];
        out[3 * BB * HH + i] = g_c[1][i];
        out[4 * BB * HH + i] = g_h3[(size_t)TT * BB * HH + i];
        out[5 * BB * HH + i] = g_c[2][i];
    }
}

// ---------------- launch ----------------
extern "C" void kernel_launch(void* const* d_in, const int* in_sizes, int n_in,
                              void* d_out, int out_size) {
    const int*   X    = (const int*)  d_in[0];
    const float* W1   = (const float*)d_in[1];
    const float* b1   = (const float*)d_in[2];
    const float* W2   = (const float*)d_in[3];
    const float* b2   = (const float*)d_in[4];
    const float* W3   = (const float*)d_in[5];
    const float* b3   = (const float*)d_in[6];
    const float* Wout = (const float*)d_in[7];
    const float* bout = (const float*)d_in[8];
    float* out = (float*)d_out;
    (void)in_sizes; (void)n_in;

    static int attr_done = 0;
    if (!attr_done) {
        cudaFuncSetAttribute(lstm_persist, cudaFuncAttributeMaxDynamicSharedMemorySize, 84096);
        attr_done = 1;
    }

    init_zero<<<256, 256>>>();

    dim3 wgrid((2u * HH * GG + 255) / 256, 3);
    wconv<<<wgrid, 256>>>(W1, W2, W3);

    lstm_persist<<<NBLK, NTHR, 84096>>>(X, W1, b1, b2, b3);

    dim3 out_grid(VV / 64, (TT * BB) / 64);
    out_gemm<<<out_grid, 128>>>(Wout, bout, out);

    long long need = (long long)TT * BB * VV + 6LL * BB * HH;
    if ((long long)out_size >= need) {
        copy_states<<<(BB * HH + 255) / 256, 256>>>(out + (size_t)TT * BB * VV);
    }
}

// round 7
// speedup vs baseline: 2.7186x; 1.0097x over previous
#include <cuda_runtime.h>
#include <cuda_bf16.h>
#include <math.h>
#include <stdint.h>

#define BB 64
#define HH 1024
#define VV 2048
#define TT 256
#define GG 4096
#define NBLK 128
#define NTHR 256

typedef unsigned long long u64;
typedef unsigned int u32;

// ---------------- device globals ----------------
__device__ __align__(128) unsigned char g_w0img[16u * 1024 * 1024];
__device__ __align__(128) unsigned char g_w1img[32u * 1024 * 1024];
__device__ __align__(128) unsigned char g_w2img[32u * 1024 * 1024];
__device__ __align__(128) unsigned char g_img1[2][16 * 16384];
__device__ __align__(128) unsigned char g_img2[2][16 * 16384];
__device__ __align__(128) unsigned char g_img3[2][16 * 16384];
__device__ float g_c[3][BB * HH];
__device__ float g_hfin[2][BB * HH];
__device__ float g_h3[(TT + 1) * BB * HH];
__device__ float g_part[3 * 64 * 4096];
__device__ unsigned g_flag[3 * 64];

__device__ unsigned g_count = 0;
__device__ volatile unsigned g_gen = 0;

__device__ __forceinline__ u32 swz(u32 off) { return off ^ ((off >> 3) & 0x70); }

__device__ __forceinline__ u32 smem_u32(const void* p) {
    u32 r;
    asm("{ .reg .u64 t; cvta.to.shared.u64 t, %1; cvt.u32.u64 %0, t; }" : "=r"(r) : "l"(p));
    return r;
}
__device__ __forceinline__ void cp16(u32 d, const void* s) {
    asm volatile("cp.async.cg.shared.global [%0], [%1], 16;" :: "r"(d), "l"(s) : "memory");
}
__device__ __forceinline__ void cp_commit() { asm volatile("cp.async.commit_group;" ::: "memory"); }
__device__ __forceinline__ void cp_wait2()  { asm volatile("cp.async.wait_group 2;" ::: "memory"); }

__device__ __forceinline__ void ldm4(u32 addr, u32* r) {
    asm volatile("ldmatrix.sync.aligned.m8n8.x4.shared.b16 {%0,%1,%2,%3}, [%4];"
                 : "=r"(r[0]), "=r"(r[1]), "=r"(r[2]), "=r"(r[3]) : "r"(addr));
}
__device__ __forceinline__ u32 ldm_addr(u32 tilebase, int rbase, int kq, int lane) {
    int row  = rbase + (lane & 7) + ((lane >> 3) & 1) * 8;
    int colb = kq * 32 + ((lane >> 4) & 1) * 16;
    return tilebase + swz((u32)(row * 128 + colb));
}
__device__ __forceinline__ void mma16816(float* d, const u32* a, u32 b0, u32 b1) {
    asm volatile("mma.sync.aligned.m16n8k16.row.col.f32.bf16.bf16.f32 "
                 "{%0,%1,%2,%3},{%4,%5,%6,%7},{%8,%9},{%0,%1,%2,%3};"
                 : "+f"(d[0]), "+f"(d[1]), "+f"(d[2]), "+f"(d[3])
                 : "r"(a[0]), "r"(a[1]), "r"(a[2]), "r"(a[3]), "r"(b0), "r"(b1));
}

// ---------------- grid barrier ----------------
__device__ __forceinline__ void gbar() {
    __syncthreads();
    if (threadIdx.x == 0) {
        unsigned gen = g_gen;
        __threadfence();
        unsigned a = atomicAdd(&g_count, 1);
        if (a == NBLK - 1) {
            atomicExch(&g_count, 0);
            __threadfence();
            g_gen = gen + 1;
        } else {
            while (g_gen == gen) { __nanosleep(32); }
            __threadfence();
        }
    }
    __syncthreads();
}

// ---------------- init ----------------
__global__ void init_zero() {
    int i = blockIdx.x * blockDim.x + threadIdx.x;
    if (i < BB * HH) {
        g_c[0][i] = 0.f; g_c[1][i] = 0.f; g_c[2][i] = 0.f;
        g_h3[i] = 0.f;
    }
    if (i < 3 * 64) g_flag[i] = 0u;
    int n32 = 16 * 16384 / 4;
    for (int j = i; j < n32; j += gridDim.x * blockDim.x) {
        ((u32*)g_img1[0])[j] = 0u;
        ((u32*)g_img2[0])[j] = 0u;
        ((u32*)g_img3[0])[j] = 0u;
    }
}

// ---------------- weight conversion ----------------
__global__ void wconv(const float* __restrict__ W1, const float* __restrict__ W2,
                      const float* __restrict__ W3) {
    int l = blockIdx.y;
    size_t idx = (size_t)blockIdx.x * blockDim.x + threadIdx.x;
    int K = (l == 0) ? HH : 2 * HH;
    if (idx >= (size_t)K * GG) return;
    int k = (int)(idx >> 12);
    int n = (int)(idx & 4095);
    float w;
    if (l == 0)      w = W1[(size_t)(VV + k) * GG + n];
    else if (l == 1) w = W2[idx];
    else             w = W3[idx];
    __nv_bfloat16 hi = __float2bfloat16(w);
    __nv_bfloat16 lo = __float2bfloat16(w - __bfloat162float(hi));
    int g = n >> 10, u = n & 1023;
    int nt = u >> 4, jj = u & 15;
    int nc = g * 16 + jj;
    int nch = K >> 6;
    size_t base = ((size_t)nt * nch + (k >> 6)) * 16384;
    u32 off = swz((u32)(nc * 128 + (k & 63) * 2));
    unsigned char* img = (l == 0) ? g_w0img : (l == 1) ? g_w1img : g_w2img;
    *(__nv_bfloat16*)(img + base + off)        = hi;
    *(__nv_bfloat16*)(img + base + 8192 + off) = lo;
}

// ---------------- per-wave segment descriptors ----------------
struct Seg {
    const unsigned char* a;
    const unsigned char* wgt;
    int start;   // global chunk index of first chunk
    int nch;
    int l, t;
};

__device__ __forceinline__ void make_seg(Seg& s, int l, int t, int nt, int kh) {
    if (l == 0) {
        s.nch = 8;
        s.wgt = g_w0img + ((size_t)nt * 16 + (size_t)kh * 8) * 16384;
        s.a   = g_img1[t & 1] + (size_t)(kh * 8) * 16384;
    } else if (l == 1) {
        s.nch = 16;
        s.wgt = g_w1img + ((size_t)nt * 32 + (size_t)kh * 16) * 16384;
        s.a   = kh ? g_img2[t & 1] : g_img1[(t + 1) & 1];
    } else {
        s.nch = 16;
        s.wgt = g_w2img + ((size_t)nt * 32 + (size_t)kh * 16) * 16384;
        s.a   = kh ? g_img3[t & 1] : g_img2[(t + 1) & 1];
    }
    s.l = l; s.t = t;
}

__device__ __forceinline__ void prefetch_chunk(u32 sb, const Seg* segs, int ns, int g, int tid) {
    int s = 0;
    while (s < ns - 1 && g >= segs[s + 1].start) s++;
    int c = g - segs[s].start;
    const unsigned char* at = segs[s].a   + (size_t)c * 16384;
    const unsigned char* wt = segs[s].wgt + (size_t)c * 16384;
    u32 dst = sb + (u32)(g & 3) * 32768;
#pragma unroll
    for (int i = 0; i < 4; i++) {
        cp16(dst + i * 4096 + tid * 16,         at + i * 4096 + tid * 16);
        cp16(dst + 16384 + i * 4096 + tid * 16, wt + i * 4096 + tid * 16);
    }
}

// ---------------- persistent wavefront LSTM (4-stage pipeline) ----------------
__global__ void __launch_bounds__(NTHR, 1) lstm_persist(
    const int*   __restrict__ X,
    const float* __restrict__ W1,
    const float* __restrict__ b1, const float* __restrict__ b2, const float* __restrict__ b3)
{
    extern __shared__ unsigned char dynsm[];
    u32 raw = smem_u32(dynsm);
    u32 sb = (raw + 127u) & ~127u;
    float* Sm = (float*)(dynsm + (sb - raw) + 131072);   // [64 c][65 m]

    const int tid  = threadIdx.x;
    const int wid  = tid >> 5;
    const int lane = tid & 31;
    const int bid  = blockIdx.x;
    const int nt   = bid >> 1;
    const int kh   = bid & 1;
    const int j0   = nt * 16;
    const int mt   = wid >> 1;
    const int nh   = wid & 1;
    const int m0   = mt * 16;
    const int nb   = nh * 32;

    for (int w = 0; w < TT + 2; w++) {
        // build wave segments
        Seg segs[3];
        int ns = 0, total = 0;
#pragma unroll
        for (int l = 0; l < 3; l++) {
            int t = w - l;
            if (t >= 0 && t < TT) {
                make_seg(segs[ns], l, t, nt, kh);
                segs[ns].start = total;
                total += segs[ns].nch;
                ns++;
            }
        }

        // preload 3 stages
#pragma unroll
        for (int i = 0; i < 3; i++) {
            if (i < total) prefetch_chunk(sb, segs, ns, i, tid);
            cp_commit();
        }

        int g = 0;
        for (int s = 0; s < ns; s++) {
            float acc[4][4];
#pragma unroll
            for (int i = 0; i < 4; i++)
#pragma unroll
                for (int q = 0; q < 4; q++) acc[i][q] = 0.f;

            const int nch = segs[s].nch;
            for (int c = 0; c < nch; c++) {
                cp_wait2();
                __syncthreads();
                if (g + 3 < total) prefetch_chunk(sb, segs, ns, g + 3, tid);
                cp_commit();

                u32 Ahi = sb + (u32)(g & 3) * 32768;
                u32 Alo = Ahi + 8192;
                u32 Whi = Ahi + 16384;
                u32 Wlo = Ahi + 24576;
#pragma unroll
                for (int kq = 0; kq < 4; kq++) {
                    u32 ah[4], al[4], bh0[4], bh1[4], bl0[4], bl1[4];
                    ldm4(ldm_addr(Ahi, m0, kq, lane), ah);
                    ldm4(ldm_addr(Alo, m0, kq, lane), al);
                    ldm4(ldm_addr(Whi, nb, kq, lane), bh0);
                    ldm4(ldm_addr(Whi, nb + 16, kq, lane), bh1);
                    ldm4(ldm_addr(Wlo, nb, kq, lane), bl0);
                    ldm4(ldm_addr(Wlo, nb + 16, kq, lane), bl1);
                    mma16816(acc[0], ah, bh0[0], bh0[2]);
                    mma16816(acc[1], ah, bh0[1], bh0[3]);
                    mma16816(acc[2], ah, bh1[0], bh1[2]);
                    mma16816(acc[3], ah, bh1[1], bh1[3]);
                    mma16816(acc[0], ah, bl0[0], bl0[2]);
                    mma16816(acc[1], ah, bl0[1], bl0[3]);
                    mma16816(acc[2], ah, bl1[0], bl1[2]);
                    mma16816(acc[3], ah, bl1[1], bl1[3]);
                    mma16816(acc[0], al, bh0[0], bh0[2]);
                    mma16816(acc[1], al, bh0[1], bh0[3]);
                    mma16816(acc[2], al, bh1[0], bh1[2]);
                    mma16816(acc[3], al, bh1[1], bh1[3]);
                }
                g++;
            }

            // ---- epilogue: K-half exchange + gates ----
            const int l = segs[s].l;
            const int t = segs[s].t;
            const int owner = (l == 1) ? 1 : 0;
            float* pbase = g_part + ((size_t)l * 64 + nt) * 4096;
            unsigned* flag = &g_flag[l * 64 + nt];

            if (kh != owner) {
                float4* pp4 = (float4*)pbase;
#pragma unroll
                for (int nti = 0; nti < 4; nti++) {
                    float4 v = make_float4(acc[nti][0], acc[nti][1], acc[nti][2], acc[nti][3]);
                    __stcg(&pp4[tid * 4 + nti], v);
                }
                __threadfence();
                __syncthreads();
                if (tid == 0) atomicExch(flag, (unsigned)(t + 1));
            } else {
                if (tid == 0) {
                    while (*(volatile unsigned*)flag != (unsigned)(t + 1)) __nanosleep(16);
                    __threadfence();
                }
                __syncthreads();
                const float4* pp4 = (const float4*)pbase;
#pragma unroll
                for (int nti = 0; nti < 4; nti++) {
                    float4 v = __ldcg(&pp4[tid * 4 + nti]);
                    acc[nti][0] += v.x; acc[nti][1] += v.y;
                    acc[nti][2] += v.z; acc[nti][3] += v.w;
                }
                {
                    int gid = lane >> 2, tig = lane & 3;
                    int mrow = m0 + gid;
#pragma unroll
                    for (int nti = 0; nti < 4; nti++) {
                        int cc = nb + nti * 8 + tig * 2;
                        Sm[cc * 65 + mrow]           = acc[nti][0];
                        Sm[(cc + 1) * 65 + mrow]     = acc[nti][1];
                        Sm[cc * 65 + mrow + 8]       = acc[nti][2];
                        Sm[(cc + 1) * 65 + mrow + 8] = acc[nti][3];
                    }
                }
                __syncthreads();

                const float* bias = (l == 0) ? b1 : (l == 1) ? b2 : b3;
                float* cbuf = g_c[l];
                unsigned char* imgout = (l == 0) ? g_img1[(t + 1) & 1]
                                      : (l == 1) ? g_img2[(t + 1) & 1]
                                                 : g_img3[(t + 1) & 1];
#pragma unroll
                for (int i = 0; i < 4; i++) {
                    int e  = tid + i * 256;
                    int m  = e & 63;
                    int jj = e >> 6;
                    int jg = j0 + jj;
                    float f  = Sm[jj * 65 + m]        + bias[jg];
                    float ig = Sm[(16 + jj) * 65 + m] + bias[HH + jg];
                    float og = Sm[(32 + jj) * 65 + m] + bias[2 * HH + jg];
                    float ct = Sm[(48 + jj) * 65 + m] + bias[3 * HH + jg];
                    if (l == 0) {
                        int xid = X[m * TT + t];
                        const float* wrow = W1 + (size_t)xid * GG + jg;
                        f  += wrow[0];
                        ig += wrow[HH];
                        og += wrow[2 * HH];
                        ct += wrow[3 * HH];
                    }
                    int cidx = m * HH + jg;
                    float cv = cbuf[cidx];
                    float sf = 1.f / (1.f + __expf(-f));
                    float si = 1.f / (1.f + __expf(-ig));
                    float so = 1.f / (1.f + __expf(-og));
                    float cn = sf * cv + si * tanhf(ct);
                    float hn = so * tanhf(cn);
                    cbuf[cidx] = cn;

                    __nv_bfloat16 hi = __float2bfloat16(hn);
                    __nv_bfloat16 lo = __float2bfloat16(hn - __bfloat162float(hi));
                    unsigned char* cb = imgout + (size_t)(jg >> 6) * 16384;
                    u32 off = swz((u32)(m * 128 + (jg & 63) * 2));
                    *(__nv_bfloat16*)(cb + off)        = hi;
                    *(__nv_bfloat16*)(cb + 8192 + off) = lo;

                    if (l == 2) g_h3[(size_t)(t + 1) * BB * HH + cidx] = hn;
                    else if (t == TT - 1) g_hfin[l][cidx] = hn;
                }
            }
        }
        gbar();
    }
}

// ---------------- out GEMM (f32x2 SIMT) ----------------
__device__ __forceinline__ u64 ffma2(u64 a, u64 b, u64 c) {
    u64 d; asm("fma.rn.f32x2 %0, %1, %2, %3;" : "=l"(d) : "l"(a), "l"(b), "l"(c)); return d;
}
__device__ __forceinline__ u64 splat2(float w) {
    u64 d; asm("mov.b64 %0, {%1, %1};" : "=l"(d) : "f"(w)); return d;
}
__device__ __forceinline__ void unpack2(u64 v, float& lo, float& hi) {
    asm("mov.b64 {%0, %1}, %2;" : "=f"(lo), "=f"(hi) : "l"(v));
}

__global__ void __launch_bounds__(128) out_gemm(
    const float* __restrict__ Wout, const float* __restrict__ bout, float* __restrict__ out)
{
    const float* Amat = g_h3 + BB * HH;
    __shared__ __align__(16) float As[32][68];
    __shared__ __align__(16) float Ws[32][64];
    const int tid = threadIdx.x;
    const int n0 = blockIdx.x * 64;
    const int m0 = blockIdx.y * 64;
    const int tx = tid & 15;
    const int ty = tid >> 4;

    u64 acc[4][4];
#pragma unroll
    for (int pr = 0; pr < 4; pr++)
#pragma unroll
        for (int c = 0; c < 4; c++) acc[pr][c] = splat2(bout[n0 + tx * 4 + c]);

    for (int kc = 0; kc < HH; kc += 32) {
#pragma unroll
        for (int i = 0; i < 16; i++) {
            int idx = tid + i * 128;
            int r = idx >> 5, kk = idx & 31;
            As[kk][r] = Amat[(size_t)(m0 + r) * HH + kc + kk];
        }
#pragma unroll
        for (int i = 0; i < 16; i++) {
            int idx = tid + i * 128;
            int kk = idx >> 6, n = idx & 63;
            Ws[kk][n] = Wout[(size_t)(kc + kk) * VV + n0 + n];
        }
        __syncthreads();
#pragma unroll
        for (int kk = 0; kk < 32; kk++) {
            double2 xa = *(const double2*)&As[kk][ty * 8];
            double2 xb = *(const double2*)&As[kk][ty * 8 + 4];
            float4  wf = *(const float4*)&Ws[kk][tx * 4];
            u64 xp[4] = { __double_as_longlong(xa.x), __double_as_longlong(xa.y),
                          __double_as_longlong(xb.x), __double_as_longlong(xb.y) };
            u64 w0 = splat2(wf.x), w1 = splat2(wf.y), w2 = splat2(wf.z), w3 = splat2(wf.w);
#pragma unroll
            for (int pr = 0; pr < 4; pr++) {
                acc[pr][0] = ffma2(xp[pr], w0, acc[pr][0]);
                acc[pr][1] = ffma2(xp[pr], w1, acc[pr][1]);
                acc[pr][2] = ffma2(xp[pr], w2, acc[pr][2]);
                acc[pr][3] = ffma2(xp[pr], w3, acc[pr][3]);
            }
        }
        __syncthreads();
    }
#pragma unroll
    for (int pr = 0; pr < 4; pr++) {
        float lo[4], hi[4];
#pragma unroll
        for (int c = 0; c < 4; c++) unpack2(acc[pr][c], lo[c], hi[c]);
        int m = m0 + ty * 8 + pr * 2;
        *(float4*)&out[(size_t)m * VV + n0 + tx * 4]       = make_float4(lo[0], lo[1], lo[2], lo[3]);
        *(float4*)&out[(size_t)(m + 1) * VV + n0 + tx * 4] = make_float4(hi[0], hi[1], hi[2], hi[3]);
    }
}

__global__ void copy_states(float* __restrict__ out) {
    int i = blockIdx.x * blockDim.x + threadIdx.x;
    if (i < BB * HH) {
        out[0 * BB * HH + i] = g_hfin[0][i];
        out[1 * BB * HH + i] = g_c[0][i];
        out[2 * BB * HH + i] = g_hfin[1][i];
        out[3 * BB * HH + i] = g_c[1][i];
        out[4 * BB * HH + i] = g_h3[(size_t)TT * BB * HH + i];
        out[5 * BB * HH + i] = g_c[2][i];
    }
}

// ---------------- launch ----------------
extern "C" void kernel_launch(void* const* d_in, const int* in_sizes, int n_in,
                              void* d_out, int out_size) {
    const int*   X    = (const int*)  d_in[0];
    const float* W1   = (const float*)d_in[1];
    const float* b1   = (const float*)d_in[2];
    const float* W2   = (const float*)d_in[3];
    const float* b2   = (const float*)d_in[4];
    const float* W3   = (const float*)d_in[5];
    const float* b3   = (const float*)d_in[6];
    const float* Wout = (const float*)d_in[7];
    const float* bout = (const float*)d_in[8];
    float* out = (float*)d_out;
    (void)in_sizes; (void)n_in;

    static int attr_done = 0;
    if (!attr_done) {
        cudaFuncSetAttribute(lstm_persist, cudaFuncAttributeMaxDynamicSharedMemorySize, 148096);
        attr_done = 1;
    }

    init_zero<<<256, 256>>>();

    dim3 wgrid((2u * HH * GG + 255) / 256, 3);
    wconv<<<wgrid, 256>>>(W1, W2, W3);

    lstm_persist<<<NBLK, NTHR, 148096>>>(X, W1, b1, b2, b3);

    dim3 out_grid(VV / 64, (TT * BB) / 64);
    out_gemm<<<out_grid, 128>>>(Wout, bout, out);

    long long need = (long long)TT * BB * VV + 6LL * BB * HH;
    if ((long long)out_size >= need) {
        copy_states<<<(BB * HH + 255) / 256, 256>>>(out + (size_t)TT * BB * VV);
    }
}

// round 8
// speedup vs baseline: 2.8548x; 1.0501x over previous
#include <cuda_runtime.h>
#include <cuda_fp16.h>
#include <math.h>
#include <stdint.h>

#define BB 64
#define HH 1024
#define VV 2048
#define TT 256
#define GG 4096
#define NBLK 128
#define NTHR 256

typedef unsigned long long u64;
typedef unsigned int u32;

// ---------------- device globals ----------------
// W images: fp16 single, per (ntile, kchunk) 8KB tile [64 n][64 k], SW128-swizzled
__device__ __align__(128) unsigned char g_w0img[8u * 1024 * 1024];
__device__ __align__(128) unsigned char g_w1img[16u * 1024 * 1024];
__device__ __align__(128) unsigned char g_w2img[16u * 1024 * 1024];
// A images: fp16 hi/lo pair, per kchunk 16KB tile = [hi 8KB][lo 8KB] of [64 m][64 k]
__device__ __align__(128) unsigned char g_img1[2][16 * 16384];
__device__ __align__(128) unsigned char g_img2[2][16 * 16384];
__device__ __align__(128) unsigned char g_img3[2][16 * 16384];
__device__ float g_c[3][BB * HH];
__device__ float g_hfin[2][BB * HH];
__device__ float g_h3[(TT + 1) * BB * HH];
__device__ float g_part[3 * 64 * 4096];
__device__ unsigned g_flag[3 * 64];

__device__ unsigned g_count = 0;
__device__ volatile unsigned g_gen = 0;

__device__ __forceinline__ u32 swz(u32 off) { return off ^ ((off >> 3) & 0x70); }

__device__ __forceinline__ u32 smem_u32(const void* p) {
    u32 r;
    asm("{ .reg .u64 t; cvta.to.shared.u64 t, %1; cvt.u32.u64 %0, t; }" : "=r"(r) : "l"(p));
    return r;
}
__device__ __forceinline__ void cp16(u32 d, const void* s) {
    asm volatile("cp.async.cg.shared.global [%0], [%1], 16;" :: "r"(d), "l"(s) : "memory");
}
__device__ __forceinline__ void cp_commit() { asm volatile("cp.async.commit_group;" ::: "memory"); }
__device__ __forceinline__ void cp_wait2()  { asm volatile("cp.async.wait_group 2;" ::: "memory"); }

__device__ __forceinline__ void ldm4(u32 addr, u32* r) {
    asm volatile("ldmatrix.sync.aligned.m8n8.x4.shared.b16 {%0,%1,%2,%3}, [%4];"
                 : "=r"(r[0]), "=r"(r[1]), "=r"(r[2]), "=r"(r[3]) : "r"(addr));
}
__device__ __forceinline__ u32 ldm_addr(u32 tilebase, int rbase, int kq, int lane) {
    int row  = rbase + (lane & 7) + ((lane >> 3) & 1) * 8;
    int colb = kq * 32 + ((lane >> 4) & 1) * 16;
    return tilebase + swz((u32)(row * 128 + colb));
}
__device__ __forceinline__ void mma16816(float* d, const u32* a, u32 b0, u32 b1) {
    asm volatile("mma.sync.aligned.m16n8k16.row.col.f32.f16.f16.f32 "
                 "{%0,%1,%2,%3},{%4,%5,%6,%7},{%8,%9},{%0,%1,%2,%3};"
                 : "+f"(d[0]), "+f"(d[1]), "+f"(d[2]), "+f"(d[3])
                 : "r"(a[0]), "r"(a[1]), "r"(a[2]), "r"(a[3]), "r"(b0), "r"(b1));
}

// ---------------- grid barrier ----------------
__device__ __forceinline__ void gbar() {
    __syncthreads();
    if (threadIdx.x == 0) {
        unsigned gen = g_gen;
        __threadfence();
        unsigned a = atomicAdd(&g_count, 1);
        if (a == NBLK - 1) {
            atomicExch(&g_count, 0);
            __threadfence();
            g_gen = gen + 1;
        } else {
            while (g_gen == gen) { __nanosleep(32); }
            __threadfence();
        }
    }
    __syncthreads();
}

// ---------------- init ----------------
__global__ void init_zero() {
    int i = blockIdx.x * blockDim.x + threadIdx.x;
    if (i < BB * HH) {
        g_c[0][i] = 0.f; g_c[1][i] = 0.f; g_c[2][i] = 0.f;
        g_h3[i] = 0.f;
    }
    if (i < 3 * 64) g_flag[i] = 0u;
    int n32 = 16 * 16384 / 4;
    for (int j = i; j < n32; j += gridDim.x * blockDim.x) {
        ((u32*)g_img1[0])[j] = 0u;
        ((u32*)g_img2[0])[j] = 0u;
        ((u32*)g_img3[0])[j] = 0u;
    }
}

// ---------------- weight conversion (fp16, single) ----------------
__global__ void wconv(const float* __restrict__ W1, const float* __restrict__ W2,
                      const float* __restrict__ W3) {
    int l = blockIdx.y;
    size_t idx = (size_t)blockIdx.x * blockDim.x + threadIdx.x;
    int K = (l == 0) ? HH : 2 * HH;
    if (idx >= (size_t)K * GG) return;
    int k = (int)(idx >> 12);
    int n = (int)(idx & 4095);
    float w;
    if (l == 0)      w = W1[(size_t)(VV + k) * GG + n];
    else if (l == 1) w = W2[idx];
    else             w = W3[idx];
    __half hw = __float2half(w);
    int g = n >> 10, u = n & 1023;
    int nt = u >> 4, jj = u & 15;
    int nc = g * 16 + jj;
    int nch = K >> 6;
    size_t base = ((size_t)nt * nch + (k >> 6)) * 8192;
    u32 off = swz((u32)(nc * 128 + (k & 63) * 2));
    unsigned char* img = (l == 0) ? g_w0img : (l == 1) ? g_w1img : g_w2img;
    *(__half*)(img + base + off) = hw;
}

// ---------------- per-wave segment descriptors ----------------
struct Seg {
    const unsigned char* a;
    const unsigned char* wgt;
    int start;
    int nch;
    int l, t;
};

__device__ __forceinline__ void make_seg(Seg& s, int l, int t, int nt, int kh) {
    if (l == 0) {
        s.nch = 8;
        s.wgt = g_w0img + ((size_t)nt * 16 + (size_t)kh * 8) * 8192;
        s.a   = g_img1[t & 1] + (size_t)(kh * 8) * 16384;
    } else if (l == 1) {
        s.nch = 16;
        s.wgt = g_w1img + ((size_t)nt * 32 + (size_t)kh * 16) * 8192;
        s.a   = kh ? g_img2[t & 1] : g_img1[(t + 1) & 1];
    } else {
        s.nch = 16;
        s.wgt = g_w2img + ((size_t)nt * 32 + (size_t)kh * 16) * 8192;
        s.a   = kh ? g_img3[t & 1] : g_img2[(t + 1) & 1];
    }
    s.l = l; s.t = t;
}

// stage layout: stride 24576 = [A hi 8K][A lo 8K][W 8K]
__device__ __forceinline__ void prefetch_chunk(u32 sb, const Seg* segs, int ns, int g, int tid) {
    int s = 0;
    while (s < ns - 1 && g >= segs[s + 1].start) s++;
    int c = g - segs[s].start;
    const unsigned char* at = segs[s].a   + (size_t)c * 16384;
    const unsigned char* wt = segs[s].wgt + (size_t)c * 8192;
    u32 dst = sb + (u32)(g & 3) * 24576;
#pragma unroll
    for (int i = 0; i < 4; i++)
        cp16(dst + i * 4096 + tid * 16, at + i * 4096 + tid * 16);
#pragma unroll
    for (int i = 0; i < 2; i++)
        cp16(dst + 16384 + i * 4096 + tid * 16, wt + i * 4096 + tid * 16);
}

// ---------------- persistent wavefront LSTM (fp16 2-term) ----------------
__global__ void __launch_bounds__(NTHR, 1) lstm_persist(
    const int*   __restrict__ X,
    const float* __restrict__ W1,
    const float* __restrict__ b1, const float* __restrict__ b2, const float* __restrict__ b3)
{
    extern __shared__ unsigned char dynsm[];
    u32 raw = smem_u32(dynsm);
    u32 sb = (raw + 127u) & ~127u;
    float* Sm = (float*)(dynsm + (sb - raw) + 98304);   // [64 c][65 m]

    const int tid  = threadIdx.x;
    const int wid  = tid >> 5;
    const int lane = tid & 31;
    const int bid  = blockIdx.x;
    const int nt   = bid >> 1;
    const int kh   = bid & 1;
    const int j0   = nt * 16;
    const int mt   = wid >> 1;
    const int nh   = wid & 1;
    const int m0   = mt * 16;
    const int nb   = nh * 32;

    for (int w = 0; w < TT + 2; w++) {
        Seg segs[3];
        int ns = 0, total = 0;
#pragma unroll
        for (int l = 0; l < 3; l++) {
            int t = w - l;
            if (t >= 0 && t < TT) {
                make_seg(segs[ns], l, t, nt, kh);
                segs[ns].start = total;
                total += segs[ns].nch;
                ns++;
            }
        }

#pragma unroll
        for (int i = 0; i < 3; i++) {
            if (i < total) prefetch_chunk(sb, segs, ns, i, tid);
            cp_commit();
        }

        int g = 0;
        for (int s = 0; s < ns; s++) {
            float acc[4][4];
#pragma unroll
            for (int i = 0; i < 4; i++)
#pragma unroll
                for (int q = 0; q < 4; q++) acc[i][q] = 0.f;

            const int nch = segs[s].nch;
            for (int c = 0; c < nch; c++) {
                cp_wait2();
                __syncthreads();
                if (g + 3 < total) prefetch_chunk(sb, segs, ns, g + 3, tid);
                cp_commit();

                u32 Ahi = sb + (u32)(g & 3) * 24576;
                u32 Alo = Ahi + 8192;
                u32 Wt  = Ahi + 16384;
#pragma unroll
                for (int kq = 0; kq < 4; kq++) {
                    u32 ah[4], al[4], b0[4], b1[4];
                    ldm4(ldm_addr(Ahi, m0, kq, lane), ah);
                    ldm4(ldm_addr(Alo, m0, kq, lane), al);
                    ldm4(ldm_addr(Wt, nb, kq, lane), b0);
                    ldm4(ldm_addr(Wt, nb + 16, kq, lane), b1);
                    mma16816(acc[0], ah, b0[0], b0[2]);
                    mma16816(acc[1], ah, b0[1], b0[3]);
                    mma16816(acc[2], ah, b1[0], b1[2]);
                    mma16816(acc[3], ah, b1[1], b1[3]);
                    mma16816(acc[0], al, b0[0], b0[2]);
                    mma16816(acc[1], al, b0[1], b0[3]);
                    mma16816(acc[2], al, b1[0], b1[2]);
                    mma16816(acc[3], al, b1[1], b1[3]);
                }
                g++;
            }

            // ---- epilogue: K-half exchange + gates ----
            const int l = segs[s].l;
            const int t = segs[s].t;
            const int owner = (l == 1) ? 1 : 0;
            float* pbase = g_part + ((size_t)l * 64 + nt) * 4096;
            unsigned* flag = &g_flag[l * 64 + nt];

            if (kh != owner) {
                float4* pp4 = (float4*)pbase;
#pragma unroll
                for (int nti = 0; nti < 4; nti++) {
                    float4 v = make_float4(acc[nti][0], acc[nti][1], acc[nti][2], acc[nti][3]);
                    __stcg(&pp4[tid * 4 + nti], v);
                }
                __threadfence();
                __syncthreads();
                if (tid == 0) atomicExch(flag, (unsigned)(t + 1));
            } else {
                if (tid == 0) {
                    while (*(volatile unsigned*)flag != (unsigned)(t + 1)) __nanosleep(16);
                    __threadfence();
                }
                __syncthreads();
                const float4* pp4 = (const float4*)pbase;
#pragma unroll
                for (int nti = 0; nti < 4; nti++) {
                    float4 v = __ldcg(&pp4[tid * 4 + nti]);
                    acc[nti][0] += v.x; acc[nti][1] += v.y;
                    acc[nti][2] += v.z; acc[nti][3] += v.w;
                }
                {
                    int gid = lane >> 2, tig = lane & 3;
                    int mrow = m0 + gid;
#pragma unroll
                    for (int nti = 0; nti < 4; nti++) {
                        int cc = nb + nti * 8 + tig * 2;
                        Sm[cc * 65 + mrow]           = acc[nti][0];
                        Sm[(cc + 1) * 65 + mrow]     = acc[nti][1];
                        Sm[cc * 65 + mrow + 8]       = acc[nti][2];
                        Sm[(cc + 1) * 65 + mrow + 8] = acc[nti][3];
                    }
                }
                __syncthreads();

                const float* bias = (l == 0) ? b1 : (l == 1) ? b2 : b3;
                float* cbuf = g_c[l];
                unsigned char* imgout = (l == 0) ? g_img1[(t + 1) & 1]
                                      : (l == 1) ? g_img2[(t + 1) & 1]
                                                 : g_img3[(t + 1) & 1];
#pragma unroll
                for (int i = 0; i < 4; i++) {
                    int e  = tid + i * 256;
                    int m  = e & 63;
                    int jj = e >> 6;
                    int jg = j0 + jj;
                    float f  = Sm[jj * 65 + m]        + bias[jg];
                    float ig = Sm[(16 + jj) * 65 + m] + bias[HH + jg];
                    float og = Sm[(32 + jj) * 65 + m] + bias[2 * HH + jg];
                    float ct = Sm[(48 + jj) * 65 + m] + bias[3 * HH + jg];
                    if (l == 0) {
                        int xid = X[m * TT + t];
                        const float* wrow = W1 + (size_t)xid * GG + jg;
                        f  += wrow[0];
                        ig += wrow[HH];
                        og += wrow[2 * HH];
                        ct += wrow[3 * HH];
                    }
                    int cidx = m * HH + jg;
                    float cv = cbuf[cidx];
                    float sf = 1.f / (1.f + __expf(-f));
                    float si = 1.f / (1.f + __expf(-ig));
                    float so = 1.f / (1.f + __expf(-og));
                    float cn = sf * cv + si * tanhf(ct);
                    float hn = so * tanhf(cn);
                    cbuf[cidx] = cn;

                    __half hi = __float2half(hn);
                    __half lo = __float2half(hn - __half2float(hi));
                    unsigned char* cb = imgout + (size_t)(jg >> 6) * 16384;
                    u32 off = swz((u32)(m * 128 + (jg & 63) * 2));
                    *(__half*)(cb + off)        = hi;
                    *(__half*)(cb + 8192 + off) = lo;

                    if (l == 2) g_h3[(size_t)(t + 1) * BB * HH + cidx] = hn;
                    else if (t == TT - 1) g_hfin[l][cidx] = hn;
                }
            }
        }
        gbar();
    }
}

// ---------------- out GEMM (f32x2 SIMT) ----------------
__device__ __forceinline__ u64 ffma2(u64 a, u64 b, u64 c) {
    u64 d; asm("fma.rn.f32x2 %0, %1, %2, %3;" : "=l"(d) : "l"(a), "l"(b), "l"(c)); return d;
}
__device__ __forceinline__ u64 splat2(float w) {
    u64 d; asm("mov.b64 %0, {%1, %1};" : "=l"(d) : "f"(w)); return d;
}
__device__ __forceinline__ void unpack2(u64 v, float& lo, float& hi) {
    asm("mov.b64 {%0, %1}, %2;" : "=f"(lo), "=f"(hi) : "l"(v));
}

__global__ void __launch_bounds__(128) out_gemm(
    const float* __restrict__ Wout, const float* __restrict__ bout, float* __restrict__ out)
{
    const float* Amat = g_h3 + BB * HH;
    __shared__ __align__(16) float As[32][68];
    __shared__ __align__(16) float Ws[32][64];
    const int tid = threadIdx.x;
    const int n0 = blockIdx.x * 64;
    const int m0 = blockIdx.y * 64;
    const int tx = tid & 15;
    const int ty = tid >> 4;

    u64 acc[4][4];
#pragma unroll
    for (int pr = 0; pr < 4; pr++)
#pragma unroll
        for (int c = 0; c < 4; c++) acc[pr][c] = splat2(bout[n0 + tx * 4 + c]);

    for (int kc = 0; kc < HH; kc += 32) {
#pragma unroll
        for (int i = 0; i < 16; i++) {
            int idx = tid + i * 128;
            int r = idx >> 5, kk = idx & 31;
            As[kk][r] = Amat[(size_t)(m0 + r) * HH + kc + kk];
        }
#pragma unroll
        for (int i = 0; i < 16; i++) {
            int idx = tid + i * 128;
            int kk = idx >> 6, n = idx & 63;
            Ws[kk][n] = Wout[(size_t)(kc + kk) * VV + n0 + n];
        }
        __syncthreads();
#pragma unroll
        for (int kk = 0; kk < 32; kk++) {
            double2 xa = *(const double2*)&As[kk][ty * 8];
            double2 xb = *(const double2*)&As[kk][ty * 8 + 4];
            float4  wf = *(const float4*)&Ws[kk][tx * 4];
            u64 xp[4] = { __double_as_longlong(xa.x), __double_as_longlong(xa.y),
                          __double_as_longlong(xb.x), __double_as_longlong(xb.y) };
            u64 w0 = splat2(wf.x), w1 = splat2(wf.y), w2 = splat2(wf.z), w3 = splat2(wf.w);
#pragma unroll
            for (int pr = 0; pr < 4; pr++) {
                acc[pr][0] = ffma2(xp[pr], w0, acc[pr][0]);
                acc[pr][1] = ffma2(xp[pr], w1, acc[pr][1]);
                acc[pr][2] = ffma2(xp[pr], w2, acc[pr][2]);
                acc[pr][3] = ffma2(xp[pr], w3, acc[pr][3]);
            }
        }
        __syncthreads();
    }
#pragma unroll
    for (int pr = 0; pr < 4; pr++) {
        float lo[4], hi[4];
#pragma unroll
        for (int c = 0; c < 4; c++) unpack2(acc[pr][c], lo[c], hi[c]);
        int m = m0 + ty * 8 + pr * 2;
        *(float4*)&out[(size_t)m * VV + n0 + tx * 4]       = make_float4(lo[0], lo[1], lo[2], lo[3]);
        *(float4*)&out[(size_t)(m + 1) * VV + n0 + tx * 4] = make_float4(hi[0], hi[1], hi[2], hi[3]);
    }
}

__global__ void copy_states(float* __restrict__ out) {
    int i = blockIdx.x * blockDim.x + threadIdx.x;
    if (i < BB * HH) {
        out[0 * BB * HH + i] = g_hfin[0][i];
        out[1 * BB * HH + i] = g_c[0][i];
        out[2 * BB * HH + i] = g_hfin[1][i];
        out[3 * BB * HH + i] = g_c[1][i];
        out[4 * BB * HH + i] = g_h3[(size_t)TT * BB * HH + i];
        out[5 * BB * HH + i] = g_c[2][i];
    }
}

// ---------------- launch ----------------
extern "C" void kernel_launch(void* const* d_in, const int* in_sizes, int n_in,
                              void* d_out, int out_size) {
    const int*   X    = (const int*)  d_in[0];
    const float* W1   = (const float*)d_in[1];
    const float* b1   = (const float*)d_in[2];
    const float* W2   = (const float*)d_in[3];
    const float* b2   = (const float*)d_in[4];
    const float* W3   = (const float*)d_in[5];
    const float* b3   = (const float*)d_in[6];
    const float* Wout = (const float*)d_in[7];
    const float* bout = (const float*)d_in[8];
    float* out = (float*)d_out;
    (void)in_sizes; (void)n_in;

    static int attr_done = 0;
    if (!attr_done) {
        cudaFuncSetAttribute(lstm_persist, cudaFuncAttributeMaxDynamicSharedMemorySize, 115200);
        attr_done = 1;
    }

    init_zero<<<256, 256>>>();

    dim3 wgrid((2u * HH * GG + 255) / 256, 3);
    wconv<<<wgrid, 256>>>(W1, W2, W3);

    lstm_persist<<<NBLK, NTHR, 115200>>>(X, W1, b1, b2, b3);

    dim3 out_grid(VV / 64, (TT * BB) / 64);
    out_gemm<<<out_grid, 128>>>(Wout, bout, out);

    long long need = (long long)TT * BB * VV + 6LL * BB * HH;
    if ((long long)out_size >= need) {
        copy_states<<<(BB * HH + 255) / 256, 256>>>(out + (size_t)TT * BB * VV);
    }
}

// round 9
// speedup vs baseline: 2.9813x; 1.0443x over previous
#include <cuda_runtime.h>
#include <cuda_fp16.h>
#include <math.h>
#include <stdint.h>

#define BB 64
#define HH 1024
#define VV 2048
#define TT 256
#define GG 4096
#define NBLK 128
#define NTHR 256
#define STG 24576u   // stage stride: [A hi 8K][A lo 8K][W 8K]

typedef unsigned long long u64;
typedef unsigned int u32;

// ---------------- device globals ----------------
__device__ __align__(128) unsigned char g_w0img[8u * 1024 * 1024];
__device__ __align__(128) unsigned char g_w1img[16u * 1024 * 1024];
__device__ __align__(128) unsigned char g_w2img[16u * 1024 * 1024];
__device__ __align__(128) unsigned char g_img1[2][16 * 16384];
__device__ __align__(128) unsigned char g_img2[2][16 * 16384];
__device__ __align__(128) unsigned char g_img3[2][16 * 16384];
__device__ float g_c[3][BB * HH];
__device__ float g_hfin[2][BB * HH];
__device__ float g_h3[(TT + 1) * BB * HH];
__device__ float g_part[3 * 64 * 4096];
__device__ unsigned g_flag[3 * 64];

__device__ unsigned g_count = 0;
__device__ volatile unsigned g_gen = 0;

__device__ __forceinline__ u32 swz(u32 off) { return off ^ ((off >> 3) & 0x70); }

__device__ __forceinline__ u32 smem_u32(const void* p) {
    u32 r;
    asm("{ .reg .u64 t; cvta.to.shared.u64 t, %1; cvt.u32.u64 %0, t; }" : "=r"(r) : "l"(p));
    return r;
}
__device__ __forceinline__ void mbar_init(u32 a, u32 cnt) {
    asm volatile("mbarrier.init.shared.b64 [%0], %1;" :: "r"(a), "r"(cnt) : "memory");
}
__device__ __forceinline__ void mbar_expect_tx(u32 a, u32 bytes) {
    asm volatile("mbarrier.arrive.expect_tx.shared.b64 _, [%0], %1;" :: "r"(a), "r"(bytes) : "memory");
}
__device__ __forceinline__ void mbar_wait(u32 a, u32 parity) {
    u32 done;
    asm volatile("{\n\t.reg .pred p;\n\t"
                 "mbarrier.try_wait.parity.acquire.cta.shared::cta.b64 p, [%1], %2;\n\t"
                 "selp.b32 %0, 1, 0, p;\n\t}"
                 : "=r"(done) : "r"(a), "r"(parity) : "memory");
    if (!done) {
        asm volatile("{\n\t.reg .pred P1;\n\t"
                     "W_%=:\n\t"
                     "mbarrier.try_wait.parity.acquire.cta.shared::cta.b64 P1, [%0], %1, 0x989680;\n\t"
                     "@P1 bra.uni D_%=;\n\t"
                     "bra.uni W_%=;\n\t"
                     "D_%=:\n\t}" :: "r"(a), "r"(parity) : "memory");
    }
}
__device__ __forceinline__ void bulk_g2s(u32 dst, const void* src, u32 bytes, u32 mbar) {
    asm volatile("cp.async.bulk.shared::cluster.global.mbarrier::complete_tx::bytes [%0], [%1], %2, [%3];"
                 :: "r"(dst), "l"(src), "r"(bytes), "r"(mbar) : "memory");
}

__device__ __forceinline__ void ldm4(u32 addr, u32* r) {
    asm volatile("ldmatrix.sync.aligned.m8n8.x4.shared.b16 {%0,%1,%2,%3}, [%4];"
                 : "=r"(r[0]), "=r"(r[1]), "=r"(r[2]), "=r"(r[3]) : "r"(addr));
}
__device__ __forceinline__ u32 ldm_addr(u32 tilebase, int rbase, int kq, int lane) {
    int row  = rbase + (lane & 7) + ((lane >> 3) & 1) * 8;
    int colb = kq * 32 + ((lane >> 4) & 1) * 16;
    return tilebase + swz((u32)(row * 128 + colb));
}
__device__ __forceinline__ void mma16816(float* d, const u32* a, u32 b0, u32 b1) {
    asm volatile("mma.sync.aligned.m16n8k16.row.col.f32.f16.f16.f32 "
                 "{%0,%1,%2,%3},{%4,%5,%6,%7},{%8,%9},{%0,%1,%2,%3};"
                 : "+f"(d[0]), "+f"(d[1]), "+f"(d[2]), "+f"(d[3])
                 : "r"(a[0]), "r"(a[1]), "r"(a[2]), "r"(a[3]), "r"(b0), "r"(b1));
}

// ---------------- grid barrier ----------------
__device__ __forceinline__ void gbar() {
    __syncthreads();
    if (threadIdx.x == 0) {
        unsigned gen = g_gen;
        __threadfence();
        unsigned a = atomicAdd(&g_count, 1);
        if (a == NBLK - 1) {
            atomicExch(&g_count, 0);
            __threadfence();
            g_gen = gen + 1;
        } else {
            while (g_gen == gen) { __nanosleep(32); }
            __threadfence();
        }
    }
    __syncthreads();
}

// ---------------- init ----------------
__global__ void init_zero() {
    int i = blockIdx.x * blockDim.x + threadIdx.x;
    if (i < BB * HH) {
        g_c[0][i] = 0.f; g_c[1][i] = 0.f; g_c[2][i] = 0.f;
        g_h3[i] = 0.f;
    }
    if (i < 3 * 64) g_flag[i] = 0u;
    int n32 = 16 * 16384 / 4;
    for (int j = i; j < n32; j += gridDim.x * blockDim.x) {
        ((u32*)g_img1[0])[j] = 0u;
        ((u32*)g_img2[0])[j] = 0u;
        ((u32*)g_img3[0])[j] = 0u;
    }
}

// ---------------- weight conversion (fp16, single) ----------------
__global__ void wconv(const float* __restrict__ W1, const float* __restrict__ W2,
                      const float* __restrict__ W3) {
    int l = blockIdx.y;
    size_t idx = (size_t)blockIdx.x * blockDim.x + threadIdx.x;
    int K = (l == 0) ? HH : 2 * HH;
    if (idx >= (size_t)K * GG) return;
    int k = (int)(idx >> 12);
    int n = (int)(idx & 4095);
    float w;
    if (l == 0)      w = W1[(size_t)(VV + k) * GG + n];
    else if (l == 1) w = W2[idx];
    else             w = W3[idx];
    __half hw = __float2half(w);
    int g = n >> 10, u = n & 1023;
    int nt = u >> 4, jj = u & 15;
    int nc = g * 16 + jj;
    int nch = K >> 6;
    size_t base = ((size_t)nt * nch + (k >> 6)) * 8192;
    u32 off = swz((u32)(nc * 128 + (k & 63) * 2));
    unsigned char* img = (l == 0) ? g_w0img : (l == 1) ? g_w1img : g_w2img;
    *(__half*)(img + base + off) = hw;
}

// ---------------- per-wave segment descriptors ----------------
struct Seg {
    const unsigned char* a;
    const unsigned char* wgt;
    int start;
    int nch;
    int l, t;
};

__device__ __forceinline__ void make_seg(Seg& s, int l, int t, int nt, int kh) {
    if (l == 0) {
        s.nch = 8;
        s.wgt = g_w0img + ((size_t)nt * 16 + (size_t)kh * 8) * 8192;
        s.a   = g_img1[t & 1] + (size_t)(kh * 8) * 16384;
    } else if (l == 1) {
        s.nch = 16;
        s.wgt = g_w1img + ((size_t)nt * 32 + (size_t)kh * 16) * 8192;
        s.a   = kh ? g_img2[t & 1] : g_img1[(t + 1) & 1];
    } else {
        s.nch = 16;
        s.wgt = g_w2img + ((size_t)nt * 32 + (size_t)kh * 16) * 8192;
        s.a   = kh ? g_img3[t & 1] : g_img2[(t + 1) & 1];
    }
    s.l = l; s.t = t;
}

// issue one chunk's bulk loads (elected thread only)
__device__ __forceinline__ void issue_chunk(u32 sb, u32 sbar, const Seg* segs, int ns,
                                            int g, u32 gg) {
    int s = 0;
    while (s < ns - 1 && g >= segs[s + 1].start) s++;
    int c = g - segs[s].start;
    const unsigned char* at = segs[s].a   + (size_t)c * 16384;
    const unsigned char* wt = segs[s].wgt + (size_t)c * 8192;
    u32 st = (gg + (u32)g) & 3u;
    u32 mb = sbar + st * 8;
    mbar_expect_tx(mb, 24576);
    bulk_g2s(sb + st * STG,          at, 16384, mb);
    bulk_g2s(sb + st * STG + 16384,  wt, 8192,  mb);
}

// ---------------- persistent wavefront LSTM (bulk-copy pipeline) ----------------
__global__ void __launch_bounds__(NTHR, 1) lstm_persist(
    const int*   __restrict__ X,
    const float* __restrict__ W1,
    const float* __restrict__ b1, const float* __restrict__ b2, const float* __restrict__ b3)
{
    extern __shared__ unsigned char dynsm[];
    u32 raw = smem_u32(dynsm);
    u32 sb = (raw + 127u) & ~127u;
    float* Sm = (float*)(dynsm + (sb - raw) + 4 * STG);   // [64 c][65 m] = 16640B
    u32 sbar = sb + 4 * STG + 16640;                      // 4 mbarriers

    const int tid  = threadIdx.x;
    const int wid  = tid >> 5;
    const int lane = tid & 31;
    const int bid  = blockIdx.x;
    const int nt   = bid >> 1;
    const int kh   = bid & 1;
    const int j0   = nt * 16;
    const int mt   = wid >> 1;
    const int nh   = wid & 1;
    const int m0   = mt * 16;
    const int nb   = nh * 32;

    if (tid == 0) {
#pragma unroll
        for (int s = 0; s < 4; s++) mbar_init(sbar + s * 8, 1);
    }
    __syncthreads();

    u32 gg = 0;   // persistent chunk counter (stage/parity tracking)

    for (int w = 0; w < TT + 2; w++) {
        Seg segs[3];
        int ns = 0, total = 0;
#pragma unroll
        for (int l = 0; l < 3; l++) {
            int t = w - l;
            if (t >= 0 && t < TT) {
                make_seg(segs[ns], l, t, nt, kh);
                segs[ns].start = total;
                total += segs[ns].nch;
                ns++;
            }
        }

        // preload 3 stages
        if (tid == 0) {
#pragma unroll
            for (int i = 0; i < 3; i++)
                if (i < total) issue_chunk(sb, sbar, segs, ns, i, gg);
        }

        int g = 0;
        for (int s = 0; s < ns; s++) {
            float acc[4][4];
#pragma unroll
            for (int i = 0; i < 4; i++)
#pragma unroll
                for (int q = 0; q < 4; q++) acc[i][q] = 0.f;

            const int nch = segs[s].nch;
            for (int c = 0; c < nch; c++) {
                __syncthreads();   // all warps done reading stage (g-1)&3
                if (tid == 0 && g + 3 < total)
                    issue_chunk(sb, sbar, segs, ns, g + 3, gg);

                u32 cur = (gg + (u32)g) & 3u;
                mbar_wait(sbar + cur * 8, ((gg + (u32)g) >> 2) & 1u);

                u32 Ahi = sb + cur * STG;
                u32 Alo = Ahi + 8192;
                u32 Wt  = Ahi + 16384;
#pragma unroll
                for (int kq = 0; kq < 4; kq++) {
                    u32 ah[4], al[4], b0[4], b1[4];
                    ldm4(ldm_addr(Ahi, m0, kq, lane), ah);
                    ldm4(ldm_addr(Alo, m0, kq, lane), al);
                    ldm4(ldm_addr(Wt, nb, kq, lane), b0);
                    ldm4(ldm_addr(Wt, nb + 16, kq, lane), b1);
                    mma16816(acc[0], ah, b0[0], b0[2]);
                    mma16816(acc[1], ah, b0[1], b0[3]);
                    mma16816(acc[2], ah, b1[0], b1[2]);
                    mma16816(acc[3], ah, b1[1], b1[3]);
                    mma16816(acc[0], al, b0[0], b0[2]);
                    mma16816(acc[1], al, b0[1], b0[3]);
                    mma16816(acc[2], al, b1[0], b1[2]);
                    mma16816(acc[3], al, b1[1], b1[3]);
                }
                g++;
            }

            // ---- epilogue: K-half exchange + gates ----
            const int l = segs[s].l;
            const int t = segs[s].t;
            const int owner = (l == 1) ? 1 : 0;
            float* pbase = g_part + ((size_t)l * 64 + nt) * 4096;
            unsigned* flag = &g_flag[l * 64 + nt];

            if (kh != owner) {
                float4* pp4 = (float4*)pbase;
#pragma unroll
                for (int nti = 0; nti < 4; nti++) {
                    float4 v = make_float4(acc[nti][0], acc[nti][1], acc[nti][2], acc[nti][3]);
                    __stcg(&pp4[tid * 4 + nti], v);
                }
                __threadfence();
                __syncthreads();
                if (tid == 0) atomicExch(flag, (unsigned)(t + 1));
            } else {
                if (tid == 0) {
                    while (*(volatile unsigned*)flag != (unsigned)(t + 1)) __nanosleep(16);
                    __threadfence();
                }
                __syncthreads();
                const float4* pp4 = (const float4*)pbase;
#pragma unroll
                for (int nti = 0; nti < 4; nti++) {
                    float4 v = __ldcg(&pp4[tid * 4 + nti]);
                    acc[nti][0] += v.x; acc[nti][1] += v.y;
                    acc[nti][2] += v.z; acc[nti][3] += v.w;
                }
                {
                    int gid = lane >> 2, tig = lane & 3;
                    int mrow = m0 + gid;
#pragma unroll
                    for (int nti = 0; nti < 4; nti++) {
                        int cc = nb + nti * 8 + tig * 2;
                        Sm[cc * 65 + mrow]           = acc[nti][0];
                        Sm[(cc + 1) * 65 + mrow]     = acc[nti][1];
                        Sm[cc * 65 + mrow + 8]       = acc[nti][2];
                        Sm[(cc + 1) * 65 + mrow + 8] = acc[nti][3];
                    }
                }
                __syncthreads();

                const float* bias = (l == 0) ? b1 : (l == 1) ? b2 : b3;
                float* cbuf = g_c[l];
                unsigned char* imgout = (l == 0) ? g_img1[(t + 1) & 1]
                                      : (l == 1) ? g_img2[(t + 1) & 1]
                                                 : g_img3[(t + 1) & 1];
#pragma unroll
                for (int i = 0; i < 4; i++) {
                    int e  = tid + i * 256;
                    int m  = e & 63;
                    int jj = e >> 6;
                    int jg = j0 + jj;
                    float f  = Sm[jj * 65 + m]        + bias[jg];
                    float ig = Sm[(16 + jj) * 65 + m] + bias[HH + jg];
                    float og = Sm[(32 + jj) * 65 + m] + bias[2 * HH + jg];
                    float ct = Sm[(48 + jj) * 65 + m] + bias[3 * HH + jg];
                    if (l == 0) {
                        int xid = X[m * TT + t];
                        const float* wrow = W1 + (size_t)xid * GG + jg;
                        f  += wrow[0];
                        ig += wrow[HH];
                        og += wrow[2 * HH];
                        ct += wrow[3 * HH];
                    }
                    int cidx = m * HH + jg;
                    float cv = cbuf[cidx];
                    float sf = 1.f / (1.f + __expf(-f));
                    float si = 1.f / (1.f + __expf(-ig));
                    float so = 1.f / (1.f + __expf(-og));
                    float cn = sf * cv + si * tanhf(ct);
                    float hn = so * tanhf(cn);
                    cbuf[cidx] = cn;

                    __half hi = __float2half(hn);
                    __half lo = __float2half(hn - __half2float(hi));
                    unsigned char* cb = imgout + (size_t)(jg >> 6) * 16384;
                    u32 off = swz((u32)(m * 128 + (jg & 63) * 2));
                    *(__half*)(cb + off)        = hi;
                    *(__half*)(cb + 8192 + off) = lo;

                    if (l == 2) g_h3[(size_t)(t + 1) * BB * HH + cidx] = hn;
                    else if (t == TT - 1) g_hfin[l][cidx] = hn;
                }
            }
        }
        gg += (u32)total;
        gbar();
    }
}

// ---------------- out GEMM (f32x2 SIMT) ----------------
__device__ __forceinline__ u64 ffma2(u64 a, u64 b, u64 c) {
    u64 d; asm("fma.rn.f32x2 %0, %1, %2, %3;" : "=l"(d) : "l"(a), "l"(b), "l"(c)); return d;
}
__device__ __forceinline__ u64 splat2(float w) {
    u64 d; asm("mov.b64 %0, {%1, %1};" : "=l"(d) : "f"(w)); return d;
}
__device__ __forceinline__ void unpack2(u64 v, float& lo, float& hi) {
    asm("mov.b64 {%0, %1}, %2;" : "=f"(lo), "=f"(hi) : "l"(v));
}

__global__ void __launch_bounds__(128) out_gemm(
    const float* __restrict__ Wout, const float* __restrict__ bout, float* __restrict__ out)
{
    const float* Amat = g_h3 + BB * HH;
    __shared__ __align__(16) float As[32][68];
    __shared__ __align__(16) float Ws[32][64];
    const int tid = threadIdx.x;
    const int n0 = blockIdx.x * 64;
    const int m0 = blockIdx.y * 64;
    const int tx = tid & 15;
    const int ty = tid >> 4;

    u64 acc[4][4];
#pragma unroll
    for (int pr = 0; pr < 4; pr++)
#pragma unroll
        for (int c = 0; c < 4; c++) acc[pr][c] = splat2(bout[n0 + tx * 4 + c]);

    for (int kc = 0; kc < HH; kc += 32) {
#pragma unroll
        for (int i = 0; i < 16; i++) {
            int idx = tid + i * 128;
            int r = idx >> 5, kk = idx & 31;
            As[kk][r] = Amat[(size_t)(m0 + r) * HH + kc + kk];
        }
#pragma unroll
        for (int i = 0; i < 16; i++) {
            int idx = tid + i * 128;
            int kk = idx >> 6, n = idx & 63;
            Ws[kk][n] = Wout[(size_t)(kc + kk) * VV + n0 + n];
        }
        __syncthreads();
#pragma unroll
        for (int kk = 0; kk < 32; kk++) {
            double2 xa = *(const double2*)&As[kk][ty * 8];
            double2 xb = *(const double2*)&As[kk][ty * 8 + 4];
            float4  wf = *(const float4*)&Ws[kk][tx * 4];
            u64 xp[4] = { __double_as_longlong(xa.x), __double_as_longlong(xa.y),
                          __double_as_longlong(xb.x), __double_as_longlong(xb.y) };
            u64 w0 = splat2(wf.x), w1 = splat2(wf.y), w2 = splat2(wf.z), w3 = splat2(wf.w);
#pragma unroll
            for (int pr = 0; pr < 4; pr++) {
                acc[pr][0] = ffma2(xp[pr], w0, acc[pr][0]);
                acc[pr][1] = ffma2(xp[pr], w1, acc[pr][1]);
                acc[pr][2] = ffma2(xp[pr], w2, acc[pr][2]);
                acc[pr][3] = ffma2(xp[pr], w3, acc[pr][3]);
            }
        }
        __syncthreads();
    }
#pragma unroll
    for (int pr = 0; pr < 4; pr++) {
        float lo[4], hi[4];
#pragma unroll
        for (int c = 0; c < 4; c++) unpack2(acc[pr][c], lo[c], hi[c]);
        int m = m0 + ty * 8 + pr * 2;
        *(float4*)&out[(size_t)m * VV + n0 + tx * 4]       = make_float4(lo[0], lo[1], lo[2], lo[3]);
        *(float4*)&out[(size_t)(m + 1) * VV + n0 + tx * 4] = make_float4(hi[0], hi[1], hi[2], hi[3]);
    }
}

__global__ void copy_states(float* __restrict__ out) {
    int i = blockIdx.x * blockDim.x + threadIdx.x;
    if (i < BB * HH) {
        out[0 * BB * HH + i] = g_hfin[0][i];
        out[1 * BB * HH + i] = g_c[0][i];
        out[2 * BB * HH + i] = g_hfin[1][i];
        out[3 * BB * HH + i] = g_c[1][i];
        out[4 * BB * HH + i] = g_h3[(size_t)TT * BB * HH + i];
        out[5 * BB * HH + i] = g_c[2][i];
    }
}

// ---------------- launch ----------------
extern "C" void kernel_launch(void* const* d_in, const int* in_sizes, int n_in,
                              void* d_out, int out_size) {
    const int*   X    = (const int*)  d_in[0];
    const float* W1   = (const float*)d_in[1];
    const float* b1   = (const float*)d_in[2];
    const float* W2   = (const float*)d_in[3];
    const float* b2   = (const float*)d_in[4];
    const float* W3   = (const float*)d_in[5];
    const float* b3   = (const float*)d_in[6];
    const float* Wout = (const float*)d_in[7];
    const float* bout = (const float*)d_in[8];
    float* out = (float*)d_out;
    (void)in_sizes; (void)n_in;

    static int attr_done = 0;
    if (!attr_done) {
        cudaFuncSetAttribute(lstm_persist, cudaFuncAttributeMaxDynamicSharedMemorySize, 115200);
        attr_done = 1;
    }

    init_zero<<<256, 256>>>();

    dim3 wgrid((2u * HH * GG + 255) / 256, 3);
    wconv<<<wgrid, 256>>>(W1, W2, W3);

    lstm_persist<<<NBLK, NTHR, 115200>>>(X, W1, b1, b2, b3);

    dim3 out_grid(VV / 64, (TT * BB) / 64);
    out_gemm<<<out_grid, 128>>>(Wout, bout, out);

    long long need = (long long)TT * BB * VV + 6LL * BB * HH;
    if ((long long)out_size >= need) {
        copy_states<<<(BB * HH + 255) / 256, 256>>>(out + (size_t)TT * BB * VV);
    }
}

// round 10
// speedup vs baseline: 3.2784x; 1.0997x over previous
#include <cuda_runtime.h>
#include <cuda_fp16.h>
#include <math.h>
#include <stdint.h>

#define BB 64
#define HH 1024
#define VV 2048
#define TT 256
#define GG 4096
#define NBLK 128
#define NTHR 512
#define STG 24576u   // stage stride: [A hi 8K][A lo 8K][W 8K]

typedef unsigned long long u64;
typedef unsigned int u32;

// ---------------- device globals ----------------
__device__ __align__(128) unsigned char g_w0img[8u * 1024 * 1024];
__device__ __align__(128) unsigned char g_w1img[16u * 1024 * 1024];
__device__ __align__(128) unsigned char g_w2img[16u * 1024 * 1024];
__device__ __align__(128) unsigned char g_img1[2][16 * 16384];
__device__ __align__(128) unsigned char g_img2[2][16 * 16384];
__device__ __align__(128) unsigned char g_img3[2][16 * 16384];
__device__ float g_c[3][BB * HH];
__device__ float g_hfin[2][BB * HH];
__device__ float g_h3[(TT + 1) * BB * HH];
__device__ float g_part[3 * 64 * 4096];
__device__ unsigned g_flag[3 * 64];

__device__ unsigned g_count = 0;
__device__ volatile unsigned g_gen = 0;

__device__ __forceinline__ u32 swz(u32 off) { return off ^ ((off >> 3) & 0x70); }

__device__ __forceinline__ u32 smem_u32(const void* p) {
    u32 r;
    asm("{ .reg .u64 t; cvta.to.shared.u64 t, %1; cvt.u32.u64 %0, t; }" : "=r"(r) : "l"(p));
    return r;
}
__device__ __forceinline__ void mbar_init(u32 a, u32 cnt) {
    asm volatile("mbarrier.init.shared.b64 [%0], %1;" :: "r"(a), "r"(cnt) : "memory");
}
__device__ __forceinline__ void mbar_expect_tx(u32 a, u32 bytes) {
    asm volatile("mbarrier.arrive.expect_tx.shared.b64 _, [%0], %1;" :: "r"(a), "r"(bytes) : "memory");
}
__device__ __forceinline__ void mbar_wait(u32 a, u32 parity) {
    u32 done;
    asm volatile("{\n\t.reg .pred p;\n\t"
                 "mbarrier.try_wait.parity.acquire.cta.shared::cta.b64 p, [%1], %2;\n\t"
                 "selp.b32 %0, 1, 0, p;\n\t}"
                 : "=r"(done) : "r"(a), "r"(parity) : "memory");
    if (!done) {
        asm volatile("{\n\t.reg .pred P1;\n\t"
                     "W_%=:\n\t"
                     "mbarrier.try_wait.parity.acquire.cta.shared::cta.b64 P1, [%0], %1, 0x989680;\n\t"
                     "@P1 bra.uni D_%=;\n\t"
                     "bra.uni W_%=;\n\t"
                     "D_%=:\n\t}" :: "r"(a), "r"(parity) : "memory");
    }
}
__device__ __forceinline__ void bulk_g2s(u32 dst, const void* src, u32 bytes, u32 mbar) {
    asm volatile("cp.async.bulk.shared::cluster.global.mbarrier::complete_tx::bytes [%0], [%1], %2, [%3];"
                 :: "r"(dst), "l"(src), "r"(bytes), "r"(mbar) : "memory");
}

__device__ __forceinline__ void ldm4(u32 addr, u32* r) {
    asm volatile("ldmatrix.sync.aligned.m8n8.x4.shared.b16 {%0,%1,%2,%3}, [%4];"
                 : "=r"(r[0]), "=r"(r[1]), "=r"(r[2]), "=r"(r[3]) : "r"(addr));
}
__device__ __forceinline__ u32 ldm_addr(u32 tilebase, int rbase, int kq, int lane) {
    int row  = rbase + (lane & 7) + ((lane >> 3) & 1) * 8;
    int colb = kq * 32 + ((lane >> 4) & 1) * 16;
    return tilebase + swz((u32)(row * 128 + colb));
}
__device__ __forceinline__ void mma16816(float* d, const u32* a, u32 b0, u32 b1) {
    asm volatile("mma.sync.aligned.m16n8k16.row.col.f32.f16.f16.f32 "
                 "{%0,%1,%2,%3},{%4,%5,%6,%7},{%8,%9},{%0,%1,%2,%3};"
                 : "+f"(d[0]), "+f"(d[1]), "+f"(d[2]), "+f"(d[3])
                 : "r"(a[0]), "r"(a[1]), "r"(a[2]), "r"(a[3]), "r"(b0), "r"(b1));
}

// ---------------- grid barrier ----------------
__device__ __forceinline__ void gbar() {
    __syncthreads();
    if (threadIdx.x == 0) {
        unsigned gen = g_gen;
        __threadfence();
        unsigned a = atomicAdd(&g_count, 1);
        if (a == NBLK - 1) {
            atomicExch(&g_count, 0);
            __threadfence();
            g_gen = gen + 1;
        } else {
            while (g_gen == gen) { __nanosleep(32); }
            __threadfence();
        }
    }
    __syncthreads();
}

// ---------------- init ----------------
__global__ void init_zero() {
    int i = blockIdx.x * blockDim.x + threadIdx.x;
    if (i < BB * HH) {
        g_c[0][i] = 0.f; g_c[1][i] = 0.f; g_c[2][i] = 0.f;
        g_h3[i] = 0.f;
    }
    if (i < 3 * 64) g_flag[i] = 0u;
    int n32 = 16 * 16384 / 4;
    for (int j = i; j < n32; j += gridDim.x * blockDim.x) {
        ((u32*)g_img1[0])[j] = 0u;
        ((u32*)g_img2[0])[j] = 0u;
        ((u32*)g_img3[0])[j] = 0u;
    }
}

// ---------------- weight conversion (fp16, single) ----------------
__global__ void wconv(const float* __restrict__ W1, const float* __restrict__ W2,
                      const float* __restrict__ W3) {
    int l = blockIdx.y;
    size_t idx = (size_t)blockIdx.x * blockDim.x + threadIdx.x;
    int K = (l == 0) ? HH : 2 * HH;
    if (idx >= (size_t)K * GG) return;
    int k = (int)(idx >> 12);
    int n = (int)(idx & 4095);
    float w;
    if (l == 0)      w = W1[(size_t)(VV + k) * GG + n];
    else if (l == 1) w = W2[idx];
    else             w = W3[idx];
    __half hw = __float2half(w);
    int g = n >> 10, u = n & 1023;
    int nt = u >> 4, jj = u & 15;
    int nc = g * 16 + jj;
    int nch = K >> 6;
    size_t base = ((size_t)nt * nch + (k >> 6)) * 8192;
    u32 off = swz((u32)(nc * 128 + (k & 63) * 2));
    unsigned char* img = (l == 0) ? g_w0img : (l == 1) ? g_w1img : g_w2img;
    *(__half*)(img + base + off) = hw;
}

// ---------------- per-wave segment descriptors ----------------
struct Seg {
    const unsigned char* a;
    const unsigned char* wgt;
    int start;
    int nch;
    int l, t;
};

__device__ __forceinline__ void make_seg(Seg& s, int l, int t, int nt, int kh) {
    if (l == 0) {
        s.nch = 8;
        s.wgt = g_w0img + ((size_t)nt * 16 + (size_t)kh * 8) * 8192;
        s.a   = g_img1[t & 1] + (size_t)(kh * 8) * 16384;
    } else if (l == 1) {
        s.nch = 16;
        s.wgt = g_w1img + ((size_t)nt * 32 + (size_t)kh * 16) * 8192;
        s.a   = kh ? g_img2[t & 1] : g_img1[(t + 1) & 1];
    } else {
        s.nch = 16;
        s.wgt = g_w2img + ((size_t)nt * 32 + (size_t)kh * 16) * 8192;
        s.a   = kh ? g_img3[t & 1] : g_img2[(t + 1) & 1];
    }
    s.l = l; s.t = t;
}

// issue one chunk's bulk loads (elected thread only)
__device__ __forceinline__ void issue_chunk(u32 sb, u32 sbar, const Seg* segs, int ns,
                                            int g, u32 gg) {
    int s = 0;
    while (s < ns - 1 && g >= segs[s + 1].start) s++;
    int c = g - segs[s].start;
    const unsigned char* at = segs[s].a   + (size_t)c * 16384;
    const unsigned char* wt = segs[s].wgt + (size_t)c * 8192;
    u32 st = (gg + (u32)g) & 3u;
    u32 mb = sbar + st * 8;
    mbar_expect_tx(mb, 24576);
    bulk_g2s(sb + st * STG,          at, 16384, mb);
    bulk_g2s(sb + st * STG + 16384,  wt, 8192,  mb);
}

// ---------------- persistent wavefront LSTM (512 threads, 16 warps) ----------------
// Warp layout: mt = wid>>2 (m tile of 16), nq = wid&3 (16-col group).
// Per warp per chunk: 12 LDSM + 16 HMMA; 4 warps per SMSP for latency hiding.
__global__ void __launch_bounds__(NTHR, 1) lstm_persist(
    const int*   __restrict__ X,
    const float* __restrict__ W1,
    const float* __restrict__ b1, const float* __restrict__ b2, const float* __restrict__ b3)
{
    extern __shared__ unsigned char dynsm[];
    u32 raw = smem_u32(dynsm);
    u32 sb = (raw + 127u) & ~127u;
    float* Sm = (float*)(dynsm + (sb - raw) + 4 * STG);   // [64 c][65 m] = 16640B
    u32 sbar = sb + 4 * STG + 16640;                      // 4 mbarriers

    const int tid  = threadIdx.x;
    const int wid  = tid >> 5;
    const int lane = tid & 31;
    const int bid  = blockIdx.x;
    const int nt   = bid >> 1;
    const int kh   = bid & 1;
    const int j0   = nt * 16;
    const int mt   = wid >> 2;        // 0..3
    const int nq   = wid & 3;         // 0..3
    const int m0   = mt * 16;
    const int nb   = nq * 16;

    if (tid == 0) {
#pragma unroll
        for (int s = 0; s < 4; s++) mbar_init(sbar + s * 8, 1);
    }
    __syncthreads();

    u32 gg = 0;

    for (int w = 0; w < TT + 2; w++) {
        Seg segs[3];
        int ns = 0, total = 0;
#pragma unroll
        for (int l = 0; l < 3; l++) {
            int t = w - l;
            if (t >= 0 && t < TT) {
                make_seg(segs[ns], l, t, nt, kh);
                segs[ns].start = total;
                total += segs[ns].nch;
                ns++;
            }
        }

        if (tid == 0) {
#pragma unroll
            for (int i = 0; i < 3; i++)
                if (i < total) issue_chunk(sb, sbar, segs, ns, i, gg);
        }

        int g = 0;
        for (int s = 0; s < ns; s++) {
            float acc[2][4];
#pragma unroll
            for (int i = 0; i < 2; i++)
#pragma unroll
                for (int q = 0; q < 4; q++) acc[i][q] = 0.f;

            const int nch = segs[s].nch;
            for (int c = 0; c < nch; c++) {
                __syncthreads();
                if (tid == 0 && g + 3 < total)
                    issue_chunk(sb, sbar, segs, ns, g + 3, gg);

                u32 cur = (gg + (u32)g) & 3u;
                mbar_wait(sbar + cur * 8, ((gg + (u32)g) >> 2) & 1u);

                u32 Ahi = sb + cur * STG;
                u32 Alo = Ahi + 8192;
                u32 Wt  = Ahi + 16384;
#pragma unroll
                for (int kq = 0; kq < 4; kq++) {
                    u32 ah[4], al[4], b[4];
                    ldm4(ldm_addr(Ahi, m0, kq, lane), ah);
                    ldm4(ldm_addr(Alo, m0, kq, lane), al);
                    ldm4(ldm_addr(Wt, nb, kq, lane), b);
                    mma16816(acc[0], ah, b[0], b[2]);
                    mma16816(acc[1], ah, b[1], b[3]);
                    mma16816(acc[0], al, b[0], b[2]);
                    mma16816(acc[1], al, b[1], b[3]);
                }
                g++;
            }

            // ---- epilogue: K-half exchange + gates ----
            const int l = segs[s].l;
            const int t = segs[s].t;
            const int owner = (l == 1) ? 1 : 0;
            float* pbase = g_part + ((size_t)l * 64 + nt) * 4096;
            unsigned* flag = &g_flag[l * 64 + nt];

            if (kh != owner) {
                // producer: dump accumulators (same tid->element mapping on both blocks)
                float4* pp4 = (float4*)pbase;
#pragma unroll
                for (int nti = 0; nti < 2; nti++) {
                    float4 v = make_float4(acc[nti][0], acc[nti][1], acc[nti][2], acc[nti][3]);
                    __stcg(&pp4[tid * 2 + nti], v);
                }
                __threadfence();
                __syncthreads();
                if (tid == 0) atomicExch(flag, (unsigned)(t + 1));
            } else {
                if (tid == 0) {
                    while (*(volatile unsigned*)flag != (unsigned)(t + 1)) __nanosleep(16);
                    __threadfence();
                }
                __syncthreads();
                const float4* pp4 = (const float4*)pbase;
#pragma unroll
                for (int nti = 0; nti < 2; nti++) {
                    float4 v = __ldcg(&pp4[tid * 2 + nti]);
                    acc[nti][0] += v.x; acc[nti][1] += v.y;
                    acc[nti][2] += v.z; acc[nti][3] += v.w;
                }
                {
                    int gid = lane >> 2, tig = lane & 3;
                    int mrow = m0 + gid;
#pragma unroll
                    for (int nti = 0; nti < 2; nti++) {
                        int cc = nb + nti * 8 + tig * 2;
                        Sm[cc * 65 + mrow]           = acc[nti][0];
                        Sm[(cc + 1) * 65 + mrow]     = acc[nti][1];
                        Sm[cc * 65 + mrow + 8]       = acc[nti][2];
                        Sm[(cc + 1) * 65 + mrow + 8] = acc[nti][3];
                    }
                }
                __syncthreads();

                const float* bias = (l == 0) ? b1 : (l == 1) ? b2 : b3;
                float* cbuf = g_c[l];
                unsigned char* imgout = (l == 0) ? g_img1[(t + 1) & 1]
                                      : (l == 1) ? g_img2[(t + 1) & 1]
                                                 : g_img3[(t + 1) & 1];
#pragma unroll
                for (int i = 0; i < 2; i++) {
                    int e  = tid + i * 512;
                    int m  = e & 63;
                    int jj = e >> 6;
                    int jg = j0 + jj;
                    float f  = Sm[jj * 65 + m]        + bias[jg];
                    float ig = Sm[(16 + jj) * 65 + m] + bias[HH + jg];
                    float og = Sm[(32 + jj) * 65 + m] + bias[2 * HH + jg];
                    float ct = Sm[(48 + jj) * 65 + m] + bias[3 * HH + jg];
                    if (l == 0) {
                        int xid = X[m * TT + t];
                        const float* wrow = W1 + (size_t)xid * GG + jg;
                        f  += wrow[0];
                        ig += wrow[HH];
                        og += wrow[2 * HH];
                        ct += wrow[3 * HH];
                    }
                    int cidx = m * HH + jg;
                    float cv = cbuf[cidx];
                    float sf = 1.f / (1.f + __expf(-f));
                    float si = 1.f / (1.f + __expf(-ig));
                    float so = 1.f / (1.f + __expf(-og));
                    float cn = sf * cv + si * tanhf(ct);
                    float hn = so * tanhf(cn);
                    cbuf[cidx] = cn;

                    __half hi = __float2half(hn);
                    __half lo = __float2half(hn - __half2float(hi));
                    unsigned char* cb = imgout + (size_t)(jg >> 6) * 16384;
                    u32 off = swz((u32)(m * 128 + (jg & 63) * 2));
                    *(__half*)(cb + off)        = hi;
                    *(__half*)(cb + 8192 + off) = lo;

                    if (l == 2) g_h3[(size_t)(t + 1) * BB * HH + cidx] = hn;
                    else if (t == TT - 1) g_hfin[l][cidx] = hn;
                }
            }
        }
        gg += (u32)total;
        gbar();
    }
}

// ---------------- out GEMM (f32x2 SIMT) ----------------
__device__ __forceinline__ u64 ffma2(u64 a, u64 b, u64 c) {
    u64 d; asm("fma.rn.f32x2 %0, %1, %2, %3;" : "=l"(d) : "l"(a), "l"(b), "l"(c)); return d;
}
__device__ __forceinline__ u64 splat2(float w) {
    u64 d; asm("mov.b64 %0, {%1, %1};" : "=l"(d) : "f"(w)); return d;
}
__device__ __forceinline__ void unpack2(u64 v, float& lo, float& hi) {
    asm("mov.b64 {%0, %1}, %2;" : "=f"(lo), "=f"(hi) : "l"(v));
}

__global__ void __launch_bounds__(128) out_gemm(
    const float* __restrict__ Wout, const float* __restrict__ bout, float* __restrict__ out)
{
    const float* Amat = g_h3 + BB * HH;
    __shared__ __align__(16) float As[32][68];
    __shared__ __align__(16) float Ws[32][64];
    const int tid = threadIdx.x;
    const int n0 = blockIdx.x * 64;
    const int m0 = blockIdx.y * 64;
    const int tx = tid & 15;
    const int ty = tid >> 4;

    u64 acc[4][4];
#pragma unroll
    for (int pr = 0; pr < 4; pr++)
#pragma unroll
        for (int c = 0; c < 4; c++) acc[pr][c] = splat2(bout[n0 + tx * 4 + c]);

    for (int kc = 0; kc < HH; kc += 32) {
#pragma unroll
        for (int i = 0; i < 16; i++) {
            int idx = tid + i * 128;
            int r = idx >> 5, kk = idx & 31;
            As[kk][r] = Amat[(size_t)(m0 + r) * HH + kc + kk];
        }
#pragma unroll
        for (int i = 0; i < 16; i++) {
            int idx = tid + i * 128;
            int kk = idx >> 6, n = idx & 63;
            Ws[kk][n] = Wout[(size_t)(kc + kk) * VV + n0 + n];
        }
        __syncthreads();
#pragma unroll
        for (int kk = 0; kk < 32; kk++) {
            double2 xa = *(const double2*)&As[kk][ty * 8];
            double2 xb = *(const double2*)&As[kk][ty * 8 + 4];
            float4  wf = *(const float4*)&Ws[kk][tx * 4];
            u64 xp[4] = { __double_as_longlong(xa.x), __double_as_longlong(xa.y),
                          __double_as_longlong(xb.x), __double_as_longlong(xb.y) };
            u64 w0 = splat2(wf.x), w1 = splat2(wf.y), w2 = splat2(wf.z), w3 = splat2(wf.w);
#pragma unroll
            for (int pr = 0; pr < 4; pr++) {
                acc[pr][0] = ffma2(xp[pr], w0, acc[pr][0]);
                acc[pr][1] = ffma2(xp[pr], w1, acc[pr][1]);
                acc[pr][2] = ffma2(xp[pr], w2, acc[pr][2]);
                acc[pr][3] = ffma2(xp[pr], w3, acc[pr][3]);
            }
        }
        __syncthreads();
    }
#pragma unroll
    for (int pr = 0; pr < 4; pr++) {
        float lo[4], hi[4];
#pragma unroll
        for (int c = 0; c < 4; c++) unpack2(acc[pr][c], lo[c], hi[c]);
        int m = m0 + ty * 8 + pr * 2;
        *(float4*)&out[(size_t)m * VV + n0 + tx * 4]       = make_float4(lo[0], lo[1], lo[2], lo[3]);
        *(float4*)&out[(size_t)(m + 1) * VV + n0 + tx * 4] = make_float4(hi[0], hi[1], hi[2], hi[3]);
    }
}

__global__ void copy_states(float* __restrict__ out) {
    int i = blockIdx.x * blockDim.x + threadIdx.x;
    if (i < BB * HH) {
        out[0 * BB * HH + i] = g_hfin[0][i];
        out[1 * BB * HH + i] = g_c[0][i];
        out[2 * BB * HH + i] = g_hfin[1][i];
        out[3 * BB * HH + i] = g_c[1][i];
        out[4 * BB * HH + i] = g_h3[(size_t)TT * BB * HH + i];
        out[5 * BB * HH + i] = g_c[2][i];
    }
}

// ---------------- launch ----------------
extern "C" void kernel_launch(void* const* d_in, const int* in_sizes, int n_in,
                              void* d_out, int out_size) {
    const int*   X    = (const int*)  d_in[0];
    const float* W1   = (const float*)d_in[1];
    const float* b1   = (const float*)d_in[2];
    const float* W2   = (const float*)d_in[3];
    const float* b2   = (const float*)d_in[4];
    const float* W3   = (const float*)d_in[5];
    const float* b3   = (const float*)d_in[6];
    const float* Wout = (const float*)d_in[7];
    const float* bout = (const float*)d_in[8];
    float* out = (float*)d_out;
    (void)in_sizes; (void)n_in;

    static int attr_done = 0;
    if (!attr_done) {
        cudaFuncSetAttribute(lstm_persist, cudaFuncAttributeMaxDynamicSharedMemorySize, 115200);
        attr_done = 1;
    }

    init_zero<<<256, 256>>>();

    dim3 wgrid((2u * HH * GG + 255) / 256, 3);
    wconv<<<wgrid, 256>>>(W1, W2, W3);

    lstm_persist<<<NBLK, NTHR, 115200>>>(X, W1, b1, b2, b3);

    dim3 out_grid(VV / 64, (TT * BB) / 64);
    out_gemm<<<out_grid, 128>>>(Wout, bout, out);

    long long need = (long long)TT * BB * VV + 6LL * BB * HH;
    if ((long long)out_size >= need) {
        copy_states<<<(BB * HH + 255) / 256, 256>>>(out + (size_t)TT * BB * VV);
    }
}